// round 1
// baseline (speedup 1.0000x reference)
#include <cuda_runtime.h>

// Problem constants
#define B_   8
#define N_   64
#define E_   256
#define L_   128
#define S_   2
#define ND_  64                    // destination copies per graph (= N)
#define ROWS_H (B_*ND_*N_)         // 32768  (b,d,n) rows
#define ROWS_E (B_*ND_*E_)         // 131072 (b,d,e) rows

// ---------------- scratch (device globals; no allocation) ----------------
__device__ float g_A   [B_*N_*L_];        // x@W1   [b,i]
__device__ float g_C   [B_*N_*L_];        // x@W2   [b,d]
__device__ float g_eenc[B_*E_*L_];        // encoded edges [b,e]
__device__ float g_gg  [B_*L_];           // encoded globals
__device__ float g_gve [S_*B_*L_];        // gg@Wg_edge + b_edge  per step
__device__ float g_gvn [S_*B_*L_];        // gg@Wg_node + b_node  per step
__device__ float g_h   [ROWS_H*(long)L_]; // node states   (16 MB)
__device__ float g_hs  [ROWS_H*(long)L_]; // h@Ws          (16 MB)
__device__ float g_hd  [ROWS_H*(long)L_]; // h@Wd          (16 MB)
__device__ float g_agg [ROWS_H*(long)L_]; // segment sums  (16 MB)
__device__ float g_ee  [ROWS_E*(long)L_]; // edge states   (64 MB)
__device__ int   g_csr_off [B_*(N_+1)];
__device__ int   g_csr_edge[B_*E_];

__device__ __forceinline__ float lrelu(float v){ return v > 0.f ? v : 0.01f*v; }

// ---------------- tiny kernels ----------------

// gg[b] = lrelu(u[b] @ Wg + bg)
__global__ void k_gg(const float* __restrict__ u, const float* __restrict__ Wg,
                     const float* __restrict__ bg){
    int b = blockIdx.x, c = threadIdx.x;
    float acc = bg[c];
    #pragma unroll 8
    for (int k = 0; k < L_; k++) acc += u[b*L_ + k] * Wg[k*L_ + c];
    g_gg[b*L_ + c] = lrelu(acc);
}

// gvec_e[s][b] = gg[b] @ We[s][384:512] + be[s];  gvec_n analogous with Wn[s][256:384]
__global__ void k_gvec(const float* __restrict__ We, const float* __restrict__ be,
                       const float* __restrict__ Wn, const float* __restrict__ bn){
    int id = blockIdx.x, c = threadIdx.x;
    int b = id & 7, s = (id >> 3) & 1, kind = id >> 4;
    const float* gg = &g_gg[b*L_];
    if (kind == 0){
        const float* W = We + (s*512 + 384)*L_;
        float acc = be[s*L_ + c];
        #pragma unroll 8
        for (int k = 0; k < L_; k++) acc += gg[k] * W[k*L_ + c];
        g_gve[(s*B_ + b)*L_ + c] = acc;
    } else {
        const float* W = Wn + (s*384 + 256)*L_;
        float acc = bn[s*L_ + c];
        #pragma unroll 8
        for (int k = 0; k < L_; k++) acc += gg[k] * W[k*L_ + c];
        g_gvn[(s*B_ + b)*L_ + c] = acc;
    }
}

// CSR by destination node, per graph (counting sort)
__global__ void k_csr(const int* __restrict__ edge_index){
    int b = threadIdx.x;
    if (b >= B_) return;
    int cnt[N_];
    for (int n = 0; n < N_; n++) cnt[n] = 0;
    const int* dst = edge_index + b*2*E_ + E_;
    for (int e = 0; e < E_; e++) cnt[dst[e]]++;
    int off = 0;
    for (int n = 0; n < N_; n++){ g_csr_off[b*(N_+1)+n] = off; off += cnt[n]; }
    g_csr_off[b*(N_+1)+N_] = off;
    for (int n = 0; n < N_; n++) cnt[n] = 0;
    for (int e = 0; e < E_; e++){
        int d = dst[e];
        g_csr_edge[b*E_ + g_csr_off[b*(N_+1)+d] + cnt[d]] = e;
        cnt[d]++;
    }
}

// h[b,d,i] = lrelu(A[b,i] + C[b,d] + sp[b,d,i]*w3 + bias)   (elementwise, float4)
__global__ void k_h0(const float* __restrict__ spdist, const float* __restrict__ w3,
                     const float* __restrict__ bias){
    int base = blockIdx.x*512 + threadIdx.x;
    #pragma unroll
    for (int it = 0; it < 2; it++){
        int idx4 = base + it*256;               // float4 index, 32 per row
        int c4  = idx4 & 31;
        int row = idx4 >> 5;                    // bd*64 + i
        int i   = row & 63;
        int bd  = row >> 6;
        int b   = bd >> 6;
        int d   = bd & 63;
        float sp = spdist[(b*N_ + d)*N_ + i];
        float4 a  = *(const float4*)&g_A[(b*N_ + i)*L_ + c4*4];
        float4 cc = *(const float4*)&g_C[bd*L_ + c4*4];
        float4 w  = *(const float4*)&w3[c4*4];
        float4 bi = *(const float4*)&bias[c4*4];
        float4 o;
        o.x = lrelu(a.x + cc.x + sp*w.x + bi.x);
        o.y = lrelu(a.y + cc.y + sp*w.y + bi.y);
        o.z = lrelu(a.z + cc.z + sp*w.z + bi.z);
        o.w = lrelu(a.w + cc.w + sp*w.w + bi.w);
        *(float4*)&g_h[(long)idx4*4] = o;
    }
}

// agg[b,d,n] = sum over incoming edges of ee
__global__ void k_agg(){
    int row = blockIdx.x;          // bd*64 + n
    int n  = row & 63;
    int bd = row >> 6;
    int b  = bd >> 6;
    int c  = threadIdx.x;
    int o0 = g_csr_off[b*(N_+1)+n], o1 = g_csr_off[b*(N_+1)+n+1];
    float s = 0.f;
    for (int j = o0; j < o1; j++){
        int e = g_csr_edge[b*E_ + j];
        s += g_ee[((long)(bd*E_ + e))*L_ + c];
    }
    g_agg[(long)row*L_ + c] = s;
}

// score + transposed store: out[b*E*N + e*N + d] = ee[b,d,e] . Wsc + bsc
__global__ void k_score(const float* __restrict__ Wsc, const float* __restrict__ bsc,
                        float* __restrict__ out){
    int gtid = blockIdx.x*256 + threadIdx.x;
    int row  = gtid >> 5;                  // one warp per row
    int lane = threadIdx.x & 31;
    float4 v = *(const float4*)&g_ee[(long)row*L_ + lane*4];
    float4 w = *(const float4*)&Wsc[lane*4];
    float s = v.x*w.x + v.y*w.y + v.z*w.z + v.w*w.w;
    #pragma unroll
    for (int o = 16; o; o >>= 1) s += __shfl_xor_sync(0xFFFFFFFFu, s, o);
    if (lane == 0){
        int e  = row & 255;
        int bd = row >> 8;
        int d  = bd & 63;
        int b  = bd >> 6;
        out[b*(E_*ND_) + e*ND_ + d] = s + bsc[0];
    }
}

// ---------------- tiled GEMM kernels (BM=32, BN=128, BK=32, 256 threads) ----------------
// thread (ty=tid>>5 in 0..7, tx=tid&31): computes rows ty*4..+3, cols tx*4..+3

#define GEMM_IDS \
    int t = threadIdx.x;               \
    int r = t >> 3, q = t & 7;         \
    int wr = t >> 5, wc = t & 31;      \
    int ty = t >> 5, tx = t & 31;

#define GEMM_FMA16(ACC, AV, WV)                                             \
    { float a0=AV.x,a1=AV.y,a2=AV.z,a3=AV.w;                                \
      float w0=WV.x,w1=WV.y,w2=WV.z,w3v=WV.w;                               \
      ACC[0][0]+=a0*w0; ACC[0][1]+=a0*w1; ACC[0][2]+=a0*w2; ACC[0][3]+=a0*w3v; \
      ACC[1][0]+=a1*w0; ACC[1][1]+=a1*w1; ACC[1][2]+=a1*w2; ACC[1][3]+=a1*w3v; \
      ACC[2][0]+=a2*w0; ACC[2][1]+=a2*w1; ACC[2][2]+=a2*w2; ACC[2][3]+=a2*w3v; \
      ACC[3][0]+=a3*w0; ACC[3][1]+=a3*w1; ACC[3][2]+=a3*w2; ACC[3][3]+=a3*w3v; }

// Dual-output GEMM, no bias/act.
// mode 0: Y=(g_A,g_C), X=Xin (rows = B*N)     mode 1: Y=(g_hs,g_hd), X=g_h (rows = ROWS_H)
__global__ void k_gemm_dual(const float* __restrict__ Xin,
                            const float* __restrict__ W1,
                            const float* __restrict__ W2, int mode){
    __shared__ float Xs[32][36];
    __shared__ float W1s[32][128];
    __shared__ float W2s[32][128];
    GEMM_IDS
    const float* X = mode ? g_h : Xin;
    int row0 = blockIdx.x * 32;
    float acc1[4][4] = {}, acc2[4][4] = {};
    for (int kc = 0; kc < L_; kc += 32){
        float4 xv = *(const float4*)&X[(long)(row0 + r)*L_ + kc + q*4];
        Xs[q*4+0][r]=xv.x; Xs[q*4+1][r]=xv.y; Xs[q*4+2][r]=xv.z; Xs[q*4+3][r]=xv.w;
        #pragma unroll
        for (int i = 0; i < 4; i++){
            int k = kc + wr + i*8;
            *(float4*)&W1s[wr+i*8][wc*4] = *(const float4*)&W1[k*L_ + wc*4];
            *(float4*)&W2s[wr+i*8][wc*4] = *(const float4*)&W2[k*L_ + wc*4];
        }
        __syncthreads();
        #pragma unroll
        for (int k = 0; k < 32; k++){
            float4 av = *(const float4*)&Xs[k][ty*4];
            float4 w1v = *(const float4*)&W1s[k][tx*4];
            float4 w2v = *(const float4*)&W2s[k][tx*4];
            GEMM_FMA16(acc1, av, w1v)
            GEMM_FMA16(acc2, av, w2v)
        }
        __syncthreads();
    }
    float* Y1 = mode ? g_hs : g_A;
    float* Y2 = mode ? g_hd : g_C;
    #pragma unroll
    for (int i = 0; i < 4; i++){
        long row = row0 + ty*4 + i;
        *(float4*)&Y1[row*L_ + tx*4] = make_float4(acc1[i][0],acc1[i][1],acc1[i][2],acc1[i][3]);
        *(float4*)&Y2[row*L_ + tx*4] = make_float4(acc2[i][0],acc2[i][1],acc2[i][2],acc2[i][3]);
    }
}

// Edge encoder: g_eenc = lrelu(edge_attr @ W + b)
__global__ void k_eenc(const float* __restrict__ X, const float* __restrict__ W,
                       const float* __restrict__ bias){
    __shared__ float Xs[32][36];
    __shared__ float Ws[32][128];
    GEMM_IDS
    int row0 = blockIdx.x * 32;
    float acc[4][4] = {};
    for (int kc = 0; kc < L_; kc += 32){
        float4 xv = *(const float4*)&X[(long)(row0 + r)*L_ + kc + q*4];
        Xs[q*4+0][r]=xv.x; Xs[q*4+1][r]=xv.y; Xs[q*4+2][r]=xv.z; Xs[q*4+3][r]=xv.w;
        #pragma unroll
        for (int i = 0; i < 4; i++){
            int k = kc + wr + i*8;
            *(float4*)&Ws[wr+i*8][wc*4] = *(const float4*)&W[k*L_ + wc*4];
        }
        __syncthreads();
        #pragma unroll
        for (int k = 0; k < 32; k++){
            float4 av = *(const float4*)&Xs[k][ty*4];
            float4 wv = *(const float4*)&Ws[k][tx*4];
            GEMM_FMA16(acc, av, wv)
        }
        __syncthreads();
    }
    float4 bi = *(const float4*)&bias[tx*4];
    #pragma unroll
    for (int i = 0; i < 4; i++){
        long row = row0 + ty*4 + i;
        float4 o;
        o.x = lrelu(acc[i][0] + bi.x);
        o.y = lrelu(acc[i][1] + bi.y);
        o.z = lrelu(acc[i][2] + bi.z);
        o.w = lrelu(acc[i][3] + bi.w);
        *(float4*)&g_eenc[row*L_ + tx*4] = o;
    }
}

// Edge update: ee_new[b,d,e] = ee_prev + lrelu(ee_prev@We + hs[b,d,src] + hd[b,d,dst] + gvec_e)
__global__ void k_edge_upd(const float* __restrict__ W,       // We part for step s  [128x128]
                           const int* __restrict__ edge_index, int s, int step0){
    __shared__ float Xs[32][36];
    __shared__ float Ws[32][128];
    __shared__ int   s_src[32], s_dst[32];
    __shared__ float s_gv[128];
    GEMM_IDS
    int row0 = blockIdx.x * 32;          // row = bd*E + e ; 32 | E so one bd per tile
    int e0 = row0 & (E_ - 1);
    int bd = row0 >> 8;
    int b  = bd >> 6;
    const float* Xbase = step0 ? g_eenc : g_ee;
    int xrow0 = step0 ? (b*E_ + e0) : row0;
    if (t < 32){
        s_src[t] = edge_index[b*2*E_ + e0 + t];
        s_dst[t] = edge_index[b*2*E_ + E_ + e0 + t];
    } else if (t < 160){
        s_gv[t-32] = g_gve[(s*B_ + b)*L_ + (t-32)];
    }
    float acc[4][4] = {};
    for (int kc = 0; kc < L_; kc += 32){
        float4 xv = *(const float4*)&Xbase[(long)(xrow0 + r)*L_ + kc + q*4];
        Xs[q*4+0][r]=xv.x; Xs[q*4+1][r]=xv.y; Xs[q*4+2][r]=xv.z; Xs[q*4+3][r]=xv.w;
        #pragma unroll
        for (int i = 0; i < 4; i++){
            int k = kc + wr + i*8;
            *(float4*)&Ws[wr+i*8][wc*4] = *(const float4*)&W[k*L_ + wc*4];
        }
        __syncthreads();
        #pragma unroll
        for (int k = 0; k < 32; k++){
            float4 av = *(const float4*)&Xs[k][ty*4];
            float4 wv = *(const float4*)&Ws[k][tx*4];
            GEMM_FMA16(acc, av, wv)
        }
        __syncthreads();
    }
    float4 gv = *(const float4*)&s_gv[tx*4];
    #pragma unroll
    for (int i = 0; i < 4; i++){
        int lr = ty*4 + i;
        long row = row0 + lr;
        float4 hv = *(const float4*)&g_hs[(long)(bd*N_ + s_src[lr])*L_ + tx*4];
        float4 dv = *(const float4*)&g_hd[(long)(bd*N_ + s_dst[lr])*L_ + tx*4];
        float4 pv = *(const float4*)&Xbase[(long)(xrow0 + lr)*L_ + tx*4];
        float4 o;
        o.x = pv.x + lrelu(acc[i][0] + hv.x + dv.x + gv.x);
        o.y = pv.y + lrelu(acc[i][1] + hv.y + dv.y + gv.y);
        o.z = pv.z + lrelu(acc[i][2] + hv.z + dv.z + gv.z);
        o.w = pv.w + lrelu(acc[i][3] + hv.w + dv.w + gv.w);
        *(float4*)&g_ee[row*L_ + tx*4] = o;
    }
}

// Node update: h += lrelu(h@Wn1 + agg@Wn2 + gvec_n)   (K=256 over two sources)
__global__ void k_node_upd(const float* __restrict__ W, int s){  // W = Wn[s], rows 0..255 used
    __shared__ float Xs[32][36];
    __shared__ float Ws[32][128];
    __shared__ float s_gv[128];
    GEMM_IDS
    int row0 = blockIdx.x * 32;          // row = bd*N + n ; 4096 rows per b
    int b = row0 >> 12;
    if (t < 128) s_gv[t] = g_gvn[(s*B_ + b)*L_ + t];
    float acc[4][4] = {};
    for (int kc = 0; kc < 256; kc += 32){
        const float* X = (kc < 128) ? g_h : g_agg;
        int kk = kc & 127;
        float4 xv = *(const float4*)&X[(long)(row0 + r)*L_ + kk + q*4];
        Xs[q*4+0][r]=xv.x; Xs[q*4+1][r]=xv.y; Xs[q*4+2][r]=xv.z; Xs[q*4+3][r]=xv.w;
        #pragma unroll
        for (int i = 0; i < 4; i++){
            int k = kc + wr + i*8;
            *(float4*)&Ws[wr+i*8][wc*4] = *(const float4*)&W[k*L_ + wc*4];
        }
        __syncthreads();
        #pragma unroll
        for (int k = 0; k < 32; k++){
            float4 av = *(const float4*)&Xs[k][ty*4];
            float4 wv = *(const float4*)&Ws[k][tx*4];
            GEMM_FMA16(acc, av, wv)
        }
        __syncthreads();
    }
    float4 gv = *(const float4*)&s_gv[tx*4];
    #pragma unroll
    for (int i = 0; i < 4; i++){
        long row = row0 + ty*4 + i;
        float4 hv = *(const float4*)&g_h[row*L_ + tx*4];
        float4 o;
        o.x = hv.x + lrelu(acc[i][0] + gv.x);
        o.y = hv.y + lrelu(acc[i][1] + gv.y);
        o.z = hv.z + lrelu(acc[i][2] + gv.z);
        o.w = hv.w + lrelu(acc[i][3] + gv.w);
        *(float4*)&g_h[row*L_ + tx*4] = o;
    }
}

// ---------------- launch ----------------
extern "C" void kernel_launch(void* const* d_in, const int* in_sizes, int n_in,
                              void* d_out, int out_size){
    const float* x          = (const float*)d_in[0];
    const float* edge_attr  = (const float*)d_in[1];
    const float* u          = (const float*)d_in[2];
    const float* spdist     = (const float*)d_in[3];
    const int*   edge_index = (const int*)  d_in[4];
    const float* W_node_enc = (const float*)d_in[5];
    const float* b_node_enc = (const float*)d_in[6];
    const float* W_edge_enc = (const float*)d_in[7];
    const float* b_edge_enc = (const float*)d_in[8];
    const float* W_glob_enc = (const float*)d_in[9];
    const float* b_glob_enc = (const float*)d_in[10];
    const float* W_edge_upd = (const float*)d_in[11];
    const float* b_edge_upd = (const float*)d_in[12];
    const float* W_node_upd = (const float*)d_in[13];
    const float* b_node_upd = (const float*)d_in[14];
    const float* W_score    = (const float*)d_in[15];
    const float* b_score    = (const float*)d_in[16];
    float* out = (float*)d_out;

    // Encoders / per-graph constants
    k_gg  <<<B_, L_>>>(u, W_glob_enc, b_glob_enc);
    k_gvec<<<2*S_*B_, L_>>>(W_edge_upd, b_edge_upd, W_node_upd, b_node_upd);
    k_gemm_dual<<<(B_*N_)/32, 256>>>(x, W_node_enc, W_node_enc + L_*L_, 0);   // A, C
    k_eenc<<<(B_*E_)/32, 256>>>(edge_attr, W_edge_enc, b_edge_enc);
    k_h0  <<<ROWS_H*L_/2048, 256>>>(spdist, W_node_enc + 256*L_, b_node_enc);
    k_csr <<<1, 32>>>(edge_index);

    for (int s = 0; s < S_; s++){
        const float* We = W_edge_upd + s*512*L_;
        const float* Wn = W_node_upd + s*384*L_;
        k_gemm_dual<<<ROWS_H/32, 256>>>(x, We + 128*L_, We + 256*L_, 1);      // hs, hd
        k_edge_upd <<<ROWS_E/32, 256>>>(We, edge_index, s, s == 0 ? 1 : 0);
        k_agg      <<<ROWS_H, L_>>>();
        k_node_upd <<<ROWS_H/32, 256>>>(Wn, s);
    }

    k_score<<<ROWS_E/8, 256>>>(W_score, b_score, out);
}

// round 4
// speedup vs baseline: 1.3252x; 1.3252x over previous
#include <cuda_runtime.h>
#include <cstdint>

// Problem constants
#define B_   8
#define N_   64
#define E_   256
#define L_   128
#define S_   2
#define ROWS_H (B_*N_*N_)          // 32768  (b,d,n) rows
#define ROWS_E (B_*N_*E_)          // 131072 (b,d,e) rows

#define PITCH 132                  // padded smem row pitch (floats)

// ---------------- scratch (device globals; no allocation) ----------------
__device__ float g_A   [B_*N_*L_];
__device__ float g_C   [B_*N_*L_];
__device__ float g_eenc[B_*E_*L_];
__device__ float g_gg  [B_*L_];
__device__ float g_gve [S_*B_*L_];
__device__ float g_gvn [S_*B_*L_];
__device__ float g_h   [ROWS_H*(long)L_];
__device__ float g_hs  [ROWS_H*(long)L_];
__device__ float g_hd  [ROWS_H*(long)L_];
__device__ float g_agg [ROWS_H*(long)L_];
__device__ float g_ee  [ROWS_E*(long)L_];
__device__ float g_Wt  [11*L_*L_];           // pre-transposed weights [n][k]
__device__ int   g_csr_off [B_*(N_+1)];
__device__ int   g_csr_edge[B_*E_];

__device__ __forceinline__ float lrelu(float v){ return v > 0.f ? v : 0.01f*v; }

__device__ __forceinline__ uint32_t smem_u32(const void* p){
    uint32_t a;
    asm("{ .reg .u64 t; cvta.to.shared.u64 t, %1; cvt.u32.u64 %0, t; }" : "=r"(a) : "l"(p));
    return a;
}
__device__ __forceinline__ uint32_t f2tf32(float f){
    uint32_t r; asm("cvt.rna.tf32.f32 %0, %1;" : "=r"(r) : "f"(f)); return r;
}

#define LDSM4(D, addr) \
    asm volatile("ldmatrix.sync.aligned.m8n8.x4.shared.b16 {%0,%1,%2,%3}, [%4];" \
        : "=r"((D)[0]),"=r"((D)[1]),"=r"((D)[2]),"=r"((D)[3]) : "r"(addr))

#define MMA_T(C, A, b0, b1) \
    asm volatile("mma.sync.aligned.m16n8k8.row.col.f32.tf32.tf32.f32 " \
        "{%0,%1,%2,%3}, {%4,%5,%6,%7}, {%8,%9}, {%0,%1,%2,%3};" \
        : "+f"((C)[0]),"+f"((C)[1]),"+f"((C)[2]),"+f"((C)[3]) \
        : "r"((A)[0]),"r"((A)[1]),"r"((A)[2]),"r"((A)[3]), "r"(b0),"r"(b1))

// ---------------- small kernels ----------------
__global__ void k_gg(const float* __restrict__ u, const float* __restrict__ Wg,
                     const float* __restrict__ bg){
    int b = blockIdx.x, c = threadIdx.x;
    float acc = bg[c];
    #pragma unroll 8
    for (int k = 0; k < L_; k++) acc += u[b*L_ + k] * Wg[k*L_ + c];
    g_gg[b*L_ + c] = lrelu(acc);
}

__global__ void k_gvec(const float* __restrict__ We, const float* __restrict__ be,
                       const float* __restrict__ Wn, const float* __restrict__ bn){
    int id = blockIdx.x, c = threadIdx.x;
    int b = id & 7, s = (id >> 3) & 1, kind = id >> 4;
    const float* gg = &g_gg[b*L_];
    if (kind == 0){
        const float* W = We + (s*512 + 384)*L_;
        float acc = be[s*L_ + c];
        #pragma unroll 8
        for (int k = 0; k < L_; k++) acc += gg[k] * W[k*L_ + c];
        g_gve[(s*B_ + b)*L_ + c] = acc;
    } else {
        const float* W = Wn + (s*384 + 256)*L_;
        float acc = bn[s*L_ + c];
        #pragma unroll 8
        for (int k = 0; k < L_; k++) acc += gg[k] * W[k*L_ + c];
        g_gvn[(s*B_ + b)*L_ + c] = acc;
    }
}

__global__ void k_csr(const int* __restrict__ edge_index){
    int b = threadIdx.x;
    if (b >= B_) return;
    int cnt[N_];
    for (int n = 0; n < N_; n++) cnt[n] = 0;
    const int* dst = edge_index + b*2*E_ + E_;
    for (int e = 0; e < E_; e++) cnt[dst[e]]++;
    int off = 0;
    for (int n = 0; n < N_; n++){ g_csr_off[b*(N_+1)+n] = off; off += cnt[n]; }
    g_csr_off[b*(N_+1)+N_] = off;
    for (int n = 0; n < N_; n++) cnt[n] = 0;
    for (int e = 0; e < E_; e++){
        int d = dst[e];
        g_csr_edge[b*E_ + g_csr_off[b*(N_+1)+d] + cnt[d]] = e;
        cnt[d]++;
    }
}

__global__ void k_h0(const float* __restrict__ spdist, const float* __restrict__ w3,
                     const float* __restrict__ bias){
    int base = blockIdx.x*512 + threadIdx.x;
    #pragma unroll
    for (int it = 0; it < 2; it++){
        int idx4 = base + it*256;
        int c4  = idx4 & 31;
        int row = idx4 >> 5;
        int i   = row & 63;
        int bd  = row >> 6;
        int b   = bd >> 6;
        int d   = bd & 63;
        float sp = spdist[(b*N_ + d)*N_ + i];
        float4 a  = *(const float4*)&g_A[(b*N_ + i)*L_ + c4*4];
        float4 cc = *(const float4*)&g_C[bd*L_ + c4*4];
        float4 w  = *(const float4*)&w3[c4*4];
        float4 bi = *(const float4*)&bias[c4*4];
        float4 o;
        o.x = lrelu(a.x + cc.x + sp*w.x + bi.x);
        o.y = lrelu(a.y + cc.y + sp*w.y + bi.y);
        o.z = lrelu(a.z + cc.z + sp*w.z + bi.z);
        o.w = lrelu(a.w + cc.w + sp*w.w + bi.w);
        *(float4*)&g_h[(long)idx4*4] = o;
    }
}

__global__ void k_agg(){
    int row = blockIdx.x;
    int n  = row & 63;
    int bd = row >> 6;
    int b  = bd >> 6;
    int c  = threadIdx.x;
    int o0 = g_csr_off[b*(N_+1)+n], o1 = g_csr_off[b*(N_+1)+n+1];
    float s = 0.f;
    for (int j = o0; j < o1; j++){
        int e = g_csr_edge[b*E_ + j];
        s += g_ee[((long)(bd*E_ + e))*L_ + c];
    }
    g_agg[(long)row*L_ + c] = s;
}

__global__ void k_score(const float* __restrict__ Wsc, const float* __restrict__ bsc,
                        float* __restrict__ out){
    int gtid = blockIdx.x*256 + threadIdx.x;
    int row  = gtid >> 5;
    int lane = threadIdx.x & 31;
    float4 v = *(const float4*)&g_ee[(long)row*L_ + lane*4];
    float4 w = *(const float4*)&Wsc[lane*4];
    float s = v.x*w.x + v.y*w.y + v.z*w.z + v.w*w.w;
    #pragma unroll
    for (int o = 16; o; o >>= 1) s += __shfl_xor_sync(0xFFFFFFFFu, s, o);
    if (lane == 0){
        int e  = row & 255;
        int bd = row >> 8;
        int d  = bd & 63;
        int b  = bd >> 6;
        out[b*(E_*N_) + e*N_ + d] = s + bsc[0];
    }
}

// SIMT dual GEMM for the tiny A/C encoder pass (512 rows) — exact fp32
__global__ void k_gemm_dual0(const float* __restrict__ X,
                             const float* __restrict__ W1,
                             const float* __restrict__ W2){
    __shared__ float Xs[32][36];
    __shared__ float W1s[32][128];
    __shared__ float W2s[32][128];
    int t = threadIdx.x;
    int r = t >> 3, q = t & 7;
    int wr = t >> 5, wc = t & 31;
    int ty = t >> 5, tx = t & 31;
    int row0 = blockIdx.x * 32;
    float acc1[4][4] = {}, acc2[4][4] = {};
    for (int kc = 0; kc < L_; kc += 32){
        float4 xv = *(const float4*)&X[(long)(row0 + r)*L_ + kc + q*4];
        Xs[q*4+0][r]=xv.x; Xs[q*4+1][r]=xv.y; Xs[q*4+2][r]=xv.z; Xs[q*4+3][r]=xv.w;
        #pragma unroll
        for (int i = 0; i < 4; i++){
            int k = kc + wr + i*8;
            *(float4*)&W1s[wr+i*8][wc*4] = *(const float4*)&W1[k*L_ + wc*4];
            *(float4*)&W2s[wr+i*8][wc*4] = *(const float4*)&W2[k*L_ + wc*4];
        }
        __syncthreads();
        #pragma unroll
        for (int k = 0; k < 32; k++){
            float4 av = *(const float4*)&Xs[k][ty*4];
            float4 w1v = *(const float4*)&W1s[k][tx*4];
            float4 w2v = *(const float4*)&W2s[k][tx*4];
            float a0=av.x,a1=av.y,a2=av.z,a3=av.w;
            #pragma unroll
            for (int ii=0; ii<4; ii++){
                float ai = ii==0?a0:ii==1?a1:ii==2?a2:a3;
                acc1[ii][0]+=ai*w1v.x; acc1[ii][1]+=ai*w1v.y; acc1[ii][2]+=ai*w1v.z; acc1[ii][3]+=ai*w1v.w;
                acc2[ii][0]+=ai*w2v.x; acc2[ii][1]+=ai*w2v.y; acc2[ii][2]+=ai*w2v.z; acc2[ii][3]+=ai*w2v.w;
            }
        }
        __syncthreads();
    }
    #pragma unroll
    for (int i = 0; i < 4; i++){
        long row = row0 + ty*4 + i;
        *(float4*)&g_A[row*L_ + tx*4] = make_float4(acc1[i][0],acc1[i][1],acc1[i][2],acc1[i][3]);
        *(float4*)&g_C[row*L_ + tx*4] = make_float4(acc2[i][0],acc2[i][1],acc2[i][2],acc2[i][3]);
    }
}

// ---------------- weight pre-transpose: g_Wt[mat][n][k] = W_src[k][n] ----------------
// mats: 0 = edge_enc; then per step s: 1+s*5 + {0:We_ee, 1:Ws, 2:Wd, 3:Wn1, 4:Wn2}
__global__ void k_wprep(const float* __restrict__ Wenc,
                        const float* __restrict__ Wedge,
                        const float* __restrict__ Wnode){
    int idx = blockIdx.x*256 + threadIdx.x;
    int mat = idx >> 14;
    int el  = idx & 16383;
    int n = el >> 7, k = el & 127;       // coalesced writes over k
    float v;
    if (mat == 0) v = Wenc[k*L_ + n];
    else {
        int m = mat - 1, s = m / 5, t = m % 5;
        if      (t == 0) v = Wedge[(s*512 +       k)*L_ + n];
        else if (t == 1) v = Wedge[(s*512 + 128 + k)*L_ + n];
        else if (t == 2) v = Wedge[(s*512 + 256 + k)*L_ + n];
        else if (t == 3) v = Wnode[(s*384 +       k)*L_ + n];
        else             v = Wnode[(s*384 + 128 + k)*L_ + n];
    }
    g_Wt[mat*16384 + n*128 + k] = v;
}

// ---------------- copy helpers ----------------
__device__ __forceinline__ void copy_tile_tf32(float* dst, const float* __restrict__ src,
                                               long src_row0, int src_pitch, int tid){
    #pragma unroll 4
    for (int i = tid; i < 4096; i += 256){
        int row = i >> 5, c4 = i & 31;
        float4 v = *(const float4*)&src[(src_row0 + row)*src_pitch + (c4<<2)];
        uint4 t;
        t.x = f2tf32(v.x); t.y = f2tf32(v.y); t.z = f2tf32(v.z); t.w = f2tf32(v.w);
        *(uint4*)&dst[row*PITCH + (c4<<2)] = t;
    }
}

// ---------------- mma.sync tf32 GEMM, 128x128 tiles, 256 threads ----------------
// TYPE 0: eenc   Y = lrelu(X@W + bias)
// TYPE 1: dual   Y = X@W ; Y2 = X@W2
// TYPE 2: edge   Y(g_ee) = X + lrelu(X@W + hs[src] + hd[dst] + gv)
// TYPE 3: node   Y(g_h) += lrelu(X@W + X2@W2 + gv)
template<int TYPE>
__global__ __launch_bounds__(256, 1) void k_mm(
    const float* __restrict__ X,  const float* __restrict__ Wt,
    const float* __restrict__ Wt2, float* __restrict__ Y, float* __restrict__ Y2,
    const float* __restrict__ aux, const int* __restrict__ edge_index,
    const float* __restrict__ X2, int step0)
{
    extern __shared__ float smem[];
    constexpr int TILEF = 128*PITCH;
    constexpr int NTILE = (TYPE == 1 || TYPE == 3) ? 3 : 2;
    float* Xs  = smem;
    float* Ws  = smem + TILEF;
    float* Ws2 = smem + 2*TILEF;             // valid only when NTILE==3
    float* s_gv  = smem + NTILE*TILEF;
    int*   s_src = (int*)(smem + NTILE*TILEF + 128);
    int*   s_dst = (int*)(smem + NTILE*TILEF + 256);

    int tid = threadIdx.x, wid = tid >> 5, lane = tid & 31;
    int row0 = blockIdx.x * 128;

    int bd = 0, b = 0, e0 = 0;
    long xrow0 = row0;
    if (TYPE == 2){
        bd = row0 >> 8; b = bd >> 6; e0 = row0 & (E_-1);
        xrow0 = step0 ? (long)(b*E_ + e0) : (long)row0;
    }

    // loads: weights (pre-transposed [n][k]) + X, tf32-rounded
    copy_tile_tf32(Ws, Wt, 0, 128, tid);
    if (TYPE == 1 || TYPE == 3) copy_tile_tf32(Ws2, Wt2, 0, 128, tid);
    copy_tile_tf32(Xs, X, xrow0, L_, tid);

    if (TYPE == 2){
        if (tid < 128){
            s_src[tid] = edge_index[b*2*E_ + e0 + tid];
            s_dst[tid] = edge_index[b*2*E_ + E_ + e0 + tid];
        } else {
            s_gv[tid-128] = aux[b*L_ + (tid-128)];
        }
    }
    if (TYPE == 3 && tid < 128) s_gv[tid] = aux[(row0 >> 12)*L_ + tid];
    __syncthreads();

    // fragment addresses
    const int rbase = (wid & 3) * 32;
    const int nbase = (wid >> 2) * 64;
    uint32_t xs_b = smem_u32(Xs), ws_b = smem_u32(Ws);
    uint32_t aA[2], aB[4];
    #pragma unroll
    for (int m = 0; m < 2; m++){
        int r = rbase + m*16 + ((lane>>3)&1)*8 + (lane&7);
        aA[m] = xs_b + (uint32_t)(r*PITCH + ((lane>>4)<<2))*4u;
    }
    #pragma unroll
    for (int p = 0; p < 4; p++){
        int r = nbase + p*16 + ((lane>>4)<<3) + (lane&7);
        aB[p] = ws_b + (uint32_t)(r*PITCH + (((lane>>3)&1)<<2))*4u;
    }

    float c[2][8][4];
    #pragma unroll
    for (int m = 0; m < 2; m++)
        #pragma unroll
        for (int nt = 0; nt < 8; nt++)
            #pragma unroll
            for (int q = 0; q < 4; q++) c[m][nt][q] = 0.f;

    auto pass = [&](uint32_t boff){
        #pragma unroll 4
        for (int k = 0; k < 16; k++){
            uint32_t A[2][4];
            #pragma unroll
            for (int m = 0; m < 2; m++) LDSM4(A[m], aA[m] + (uint32_t)k*32u);
            #pragma unroll
            for (int p = 0; p < 4; p++){
                uint32_t Bv[4];
                LDSM4(Bv, aB[p] + boff + (uint32_t)k*32u);
                #pragma unroll
                for (int m = 0; m < 2; m++){
                    MMA_T(c[m][2*p],   A[m], Bv[0], Bv[1]);
                    MMA_T(c[m][2*p+1], A[m], Bv[2], Bv[3]);
                }
            }
        }
    };

    const int trow  = lane >> 2;           // 0..7
    const int tcol2 = (lane & 3) * 2;

    auto store_raw = [&](float* __restrict__ Yp){
        #pragma unroll
        for (int m = 0; m < 2; m++){
            long rA = (long)(row0 + rbase + m*16 + trow);
            #pragma unroll
            for (int nt = 0; nt < 8; nt++){
                int col = nbase + nt*8 + tcol2;
                *(float2*)&Yp[rA*L_ + col]      = make_float2(c[m][nt][0], c[m][nt][1]);
                *(float2*)&Yp[(rA+8)*L_ + col]  = make_float2(c[m][nt][2], c[m][nt][3]);
            }
        }
    };

    pass(0);

    if (TYPE == 0){
        #pragma unroll
        for (int m = 0; m < 2; m++){
            long rA = (long)(row0 + rbase + m*16 + trow);
            #pragma unroll
            for (int nt = 0; nt < 8; nt++){
                int col = nbase + nt*8 + tcol2;
                float2 bi = *(const float2*)&aux[col];
                *(float2*)&Y[rA*L_ + col] =
                    make_float2(lrelu(c[m][nt][0]+bi.x), lrelu(c[m][nt][1]+bi.y));
                *(float2*)&Y[(rA+8)*L_ + col] =
                    make_float2(lrelu(c[m][nt][2]+bi.x), lrelu(c[m][nt][3]+bi.y));
            }
        }
    } else if (TYPE == 1){
        store_raw(Y);
        #pragma unroll
        for (int m = 0; m < 2; m++)
            #pragma unroll
            for (int nt = 0; nt < 8; nt++)
                #pragma unroll
                for (int q = 0; q < 4; q++) c[m][nt][q] = 0.f;
        pass((uint32_t)TILEF*4u);
        store_raw(Y2);
    } else if (TYPE == 2){
        long hb = (long)bd*N_*L_;
        #pragma unroll
        for (int m = 0; m < 2; m++){
            int lrA = rbase + m*16 + trow, lrB = lrA + 8;
            const float* hsA = &g_hs[hb + (long)s_src[lrA]*L_];
            const float* hdA = &g_hd[hb + (long)s_dst[lrA]*L_];
            const float* hsB = &g_hs[hb + (long)s_src[lrB]*L_];
            const float* hdB = &g_hd[hb + (long)s_dst[lrB]*L_];
            const float* pvA = &X[(xrow0 + lrA)*L_];
            const float* pvB = &X[(xrow0 + lrB)*L_];
            #pragma unroll
            for (int nt = 0; nt < 8; nt++){
                int col = nbase + nt*8 + tcol2;
                float2 gv = *(const float2*)&s_gv[col];
                float2 h1 = *(const float2*)&hsA[col];
                float2 d1 = *(const float2*)&hdA[col];
                float2 p1 = *(const float2*)&pvA[col];
                float2 o1;
                o1.x = p1.x + lrelu(c[m][nt][0] + h1.x + d1.x + gv.x);
                o1.y = p1.y + lrelu(c[m][nt][1] + h1.y + d1.y + gv.y);
                *(float2*)&Y[(long)(row0 + lrA)*L_ + col] = o1;
                float2 h2 = *(const float2*)&hsB[col];
                float2 d2 = *(const float2*)&hdB[col];
                float2 p2 = *(const float2*)&pvB[col];
                float2 o2;
                o2.x = p2.x + lrelu(c[m][nt][2] + h2.x + d2.x + gv.x);
                o2.y = p2.y + lrelu(c[m][nt][3] + h2.y + d2.y + gv.y);
                *(float2*)&Y[(long)(row0 + lrB)*L_ + col] = o2;
            }
        }
    } else { // TYPE 3: second K-chunk with X2 (agg) @ W2, then fused residual
        __syncthreads();
        copy_tile_tf32(Xs, X2, row0, L_, tid);
        __syncthreads();
        pass((uint32_t)TILEF*4u);
        #pragma unroll
        for (int m = 0; m < 2; m++){
            long rA = (long)(row0 + rbase + m*16 + trow);
            #pragma unroll
            for (int nt = 0; nt < 8; nt++){
                int col = nbase + nt*8 + tcol2;
                float2 gv = *(const float2*)&s_gv[col];
                float2 h1 = *(const float2*)&g_h[rA*L_ + col];
                float2 h2 = *(const float2*)&g_h[(rA+8)*L_ + col];
                float2 o1, o2;
                o1.x = h1.x + lrelu(c[m][nt][0] + gv.x);
                o1.y = h1.y + lrelu(c[m][nt][1] + gv.y);
                o2.x = h2.x + lrelu(c[m][nt][2] + gv.x);
                o2.y = h2.y + lrelu(c[m][nt][3] + gv.y);
                *(float2*)&Y[rA*L_ + col]     = o1;
                *(float2*)&Y[(rA+8)*L_ + col] = o2;
            }
        }
    }
}

// ---------------- launch ----------------
#define SMEM_2T ((2*128*PITCH + 384) * 4)
#define SMEM_3T ((3*128*PITCH + 384) * 4)

extern "C" void kernel_launch(void* const* d_in, const int* in_sizes, int n_in,
                              void* d_out, int out_size){
    const float* x          = (const float*)d_in[0];
    const float* edge_attr  = (const float*)d_in[1];
    const float* u          = (const float*)d_in[2];
    const float* spdist     = (const float*)d_in[3];
    const int*   edge_index = (const int*)  d_in[4];
    const float* W_node_enc = (const float*)d_in[5];
    const float* b_node_enc = (const float*)d_in[6];
    const float* W_edge_enc = (const float*)d_in[7];
    const float* b_edge_enc = (const float*)d_in[8];
    const float* W_glob_enc = (const float*)d_in[9];
    const float* b_glob_enc = (const float*)d_in[10];
    const float* W_edge_upd = (const float*)d_in[11];
    const float* b_edge_upd = (const float*)d_in[12];
    const float* W_node_upd = (const float*)d_in[13];
    const float* b_node_upd = (const float*)d_in[14];
    const float* W_score    = (const float*)d_in[15];
    const float* b_score    = (const float*)d_in[16];
    float* out = (float*)d_out;

    static int inited = 0;
    if (!inited){
        cudaFuncSetAttribute(k_mm<0>, cudaFuncAttributeMaxDynamicSharedMemorySize, SMEM_2T);
        cudaFuncSetAttribute(k_mm<1>, cudaFuncAttributeMaxDynamicSharedMemorySize, SMEM_3T);
        cudaFuncSetAttribute(k_mm<2>, cudaFuncAttributeMaxDynamicSharedMemorySize, SMEM_2T);
        cudaFuncSetAttribute(k_mm<3>, cudaFuncAttributeMaxDynamicSharedMemorySize, SMEM_3T);
        inited = 1;
    }

    float *Wt=0, *gve=0, *gvn=0, *ee0=0, *eenc0=0, *h0p=0, *hs0=0, *hd0=0, *agg0=0;
    cudaGetSymbolAddress((void**)&Wt, g_Wt);
    cudaGetSymbolAddress((void**)&gve, g_gve);
    cudaGetSymbolAddress((void**)&gvn, g_gvn);
    cudaGetSymbolAddress((void**)&ee0, g_ee);
    cudaGetSymbolAddress((void**)&eenc0, g_eenc);
    cudaGetSymbolAddress((void**)&h0p, g_h);
    cudaGetSymbolAddress((void**)&hs0, g_hs);
    cudaGetSymbolAddress((void**)&hd0, g_hd);
    cudaGetSymbolAddress((void**)&agg0, g_agg);

    k_gg   <<<B_, L_>>>(u, W_glob_enc, b_glob_enc);
    k_gvec <<<2*S_*B_, L_>>>(W_edge_upd, b_edge_upd, W_node_upd, b_node_upd);
    k_wprep<<<11*16384/256, 256>>>(W_edge_enc, W_edge_upd, W_node_upd);
    k_gemm_dual0<<<(B_*N_)/32, 256>>>(x, W_node_enc, W_node_enc + L_*L_);
    k_mm<0><<<(B_*E_)/128, 256, SMEM_2T>>>(edge_attr, Wt + 0*16384, 0,
                                           eenc0, 0, b_edge_enc, 0, 0, 0);
    k_h0   <<<ROWS_H*L_/2048, 256>>>(spdist, W_node_enc + 256*L_, b_node_enc);
    k_csr  <<<1, 32>>>(edge_index);

    for (int s = 0; s < S_; s++){
        float* We_ee = Wt + (1 + s*5 + 0)*16384;
        float* Ws_   = Wt + (1 + s*5 + 1)*16384;
        float* Wd_   = Wt + (1 + s*5 + 2)*16384;
        float* Wn1   = Wt + (1 + s*5 + 3)*16384;
        float* Wn2   = Wt + (1 + s*5 + 4)*16384;

        k_mm<1><<<ROWS_H/128, 256, SMEM_3T>>>(h0p, Ws_, Wd_, hs0, hd0, 0, 0, 0, 0);
        k_mm<2><<<ROWS_E/128, 256, SMEM_2T>>>(s == 0 ? eenc0 : ee0, We_ee, 0,
                                              ee0, 0, gve + s*B_*L_, edge_index, 0, s == 0 ? 1 : 0);
        k_agg  <<<ROWS_H, L_>>>();
        k_mm<3><<<ROWS_H/128, 256, SMEM_3T>>>(h0p, Wn1, Wn2, h0p, 0,
                                              gvn + s*B_*L_, 0, agg0, 0);
    }

    k_score<<<ROWS_E/8, 256>>>(W_score, b_score, out);
}

// round 5
// speedup vs baseline: 2.3411x; 1.7666x over previous
#include <cuda_runtime.h>
#include <cstdint>

#define B_   8
#define N_   64
#define E_   256
#define L_   128
#define PITCH  132
#define WPITCH 68

// ---------------- device globals ----------------
__device__ float g_A   [512*128];
__device__ float g_C   [512*128];
__device__ float g_eenc[2048*128];
__device__ float g_gg  [8*128];
__device__ float g_gve [2*8*128];
__device__ float g_gvn [2*8*128];
__device__ float g_ee  [512*256*128];
__device__ float g_Wt  [11*128*128];
__device__ int   g_csr_off [8*65];
__device__ int   g_csr_edge[8*256];

__device__ __forceinline__ float lrelu(float v){ return v > 0.f ? v : 0.01f*v; }
__device__ __forceinline__ uint32_t smem_u32(const void* p){
    uint32_t a;
    asm("{ .reg .u64 t; cvta.to.shared.u64 t, %1; cvt.u32.u64 %0, t; }" : "=r"(a) : "l"(p));
    return a;
}
__device__ __forceinline__ uint32_t f2tf32(float f){
    uint32_t r; asm("cvt.rna.tf32.f32 %0, %1;" : "=r"(r) : "f"(f)); return r;
}
__device__ __forceinline__ uint32_t tf32r(uint32_t x){
    uint32_t r; asm("cvt.rna.tf32.f32 %0, %1;" : "=r"(r) : "f"(__uint_as_float(x))); return r;
}

#define LDSM4(D, addr) \
    asm volatile("ldmatrix.sync.aligned.m8n8.x4.shared.b16 {%0,%1,%2,%3}, [%4];" \
        : "=r"((D)[0]),"=r"((D)[1]),"=r"((D)[2]),"=r"((D)[3]) : "r"(addr))

#define MMA_T(C, A, b0, b1) \
    asm volatile("mma.sync.aligned.m16n8k8.row.col.f32.tf32.tf32.f32 " \
        "{%0,%1,%2,%3}, {%4,%5,%6,%7}, {%8,%9}, {%0,%1,%2,%3};" \
        : "+f"((C)[0]),"+f"((C)[1]),"+f"((C)[2]),"+f"((C)[3]) \
        : "r"((A)[0]),"r"((A)[1]),"r"((A)[2]),"r"((A)[3]), "r"(b0),"r"(b1))

// ---------------- shared gemm pieces ----------------
__device__ __forceinline__ void load_wchunk(float* s_w, const float* __restrict__ Wmat,
                                            int kc, int tid){
    const float* Wp = Wmat + kc;
    #pragma unroll
    for (int i = tid; i < 2048; i += 256){
        int n = i >> 4, k4 = i & 15;
        *(float4*)&s_w[n*WPITCH + k4*4] = *(const float4*)&Wp[n*128 + k4*4];
    }
}

__device__ __forceinline__ void gemm128_chunk(float c[2][8][4], const uint32_t aA[2],
                                              const uint32_t aB[4], int kc){
    #pragma unroll
    for (int k = 0; k < 8; k++){
        uint32_t A[2][4];
        #pragma unroll
        for (int m = 0; m < 2; m++){
            LDSM4(A[m], aA[m] + (uint32_t)(kc + k*8)*4u);
            A[m][0]=tf32r(A[m][0]); A[m][1]=tf32r(A[m][1]);
            A[m][2]=tf32r(A[m][2]); A[m][3]=tf32r(A[m][3]);
        }
        #pragma unroll
        for (int p = 0; p < 4; p++){
            uint32_t Bv[4];
            LDSM4(Bv, aB[p] + (uint32_t)k*32u);
            #pragma unroll
            for (int m = 0; m < 2; m++){
                MMA_T(c[m][2*p],   A[m], Bv[0], Bv[1]);
                MMA_T(c[m][2*p+1], A[m], Bv[2], Bv[3]);
            }
        }
    }
}

__device__ __forceinline__ void gemm64_chunk(float c[2][4][4], const uint32_t aA[2],
                                             const uint32_t aB[2], int kc){
    #pragma unroll
    for (int k = 0; k < 8; k++){
        uint32_t A[2][4];
        #pragma unroll
        for (int m = 0; m < 2; m++){
            LDSM4(A[m], aA[m] + (uint32_t)(kc + k*8)*4u);
            A[m][0]=tf32r(A[m][0]); A[m][1]=tf32r(A[m][1]);
            A[m][2]=tf32r(A[m][2]); A[m][3]=tf32r(A[m][3]);
        }
        #pragma unroll
        for (int p = 0; p < 2; p++){
            uint32_t Bv[4];
            LDSM4(Bv, aB[p] + (uint32_t)k*32u);
            #pragma unroll
            for (int m = 0; m < 2; m++){
                MMA_T(c[m][2*p],   A[m], Bv[0], Bv[1]);
                MMA_T(c[m][2*p+1], A[m], Bv[2], Bv[3]);
            }
        }
    }
}

// ---------------- small pre-kernels ----------------
__global__ void k_gg(const float* __restrict__ u, const float* __restrict__ Wg,
                     const float* __restrict__ bg){
    int b = blockIdx.x, c = threadIdx.x;
    float acc = bg[c];
    #pragma unroll 8
    for (int k = 0; k < L_; k++) acc += u[b*L_ + k] * Wg[k*L_ + c];
    g_gg[b*L_ + c] = lrelu(acc);
}

__global__ void k_gvec(const float* __restrict__ We, const float* __restrict__ be,
                       const float* __restrict__ Wn, const float* __restrict__ bn){
    int id = blockIdx.x, c = threadIdx.x;
    int b = id & 7, s = (id >> 3) & 1, kind = id >> 4;
    const float* gg = &g_gg[b*L_];
    if (kind == 0){
        const float* W = We + (s*512 + 384)*L_;
        float acc = be[s*L_ + c];
        #pragma unroll 8
        for (int k = 0; k < L_; k++) acc += gg[k] * W[k*L_ + c];
        g_gve[(s*B_ + b)*L_ + c] = acc;
    } else {
        const float* W = Wn + (s*384 + 256)*L_;
        float acc = bn[s*L_ + c];
        #pragma unroll 8
        for (int k = 0; k < L_; k++) acc += gg[k] * W[k*L_ + c];
        g_gvn[(s*B_ + b)*L_ + c] = acc;
    }
}

__global__ void k_csr(const int* __restrict__ edge_index){
    int b = threadIdx.x;
    if (b >= B_) return;
    int cnt[N_];
    for (int n = 0; n < N_; n++) cnt[n] = 0;
    const int* dst = edge_index + b*2*E_ + E_;
    for (int e = 0; e < E_; e++) cnt[dst[e]]++;
    int off = 0;
    for (int n = 0; n < N_; n++){ g_csr_off[b*65+n] = off; off += cnt[n]; }
    g_csr_off[b*65+N_] = off;
    for (int n = 0; n < N_; n++) cnt[n] = 0;
    for (int e = 0; e < E_; e++){
        int d = dst[e];
        g_csr_edge[b*E_ + g_csr_off[b*65+d] + cnt[d]] = e;
        cnt[d]++;
    }
}

// weights pre-transposed [n][k] and RNA-rounded to tf32
__global__ void k_wprep(const float* __restrict__ Wenc,
                        const float* __restrict__ Wedge,
                        const float* __restrict__ Wnode){
    int idx = blockIdx.x*256 + threadIdx.x;
    int mat = idx >> 14;
    int el  = idx & 16383;
    int n = el >> 7, k = el & 127;
    float v;
    if (mat == 0) v = Wenc[k*L_ + n];
    else {
        int m = mat - 1, s = m / 5, t = m % 5;
        if      (t == 0) v = Wedge[(s*512 +       k)*L_ + n];
        else if (t == 1) v = Wedge[(s*512 + 128 + k)*L_ + n];
        else if (t == 2) v = Wedge[(s*512 + 256 + k)*L_ + n];
        else if (t == 3) v = Wnode[(s*384 +       k)*L_ + n];
        else             v = Wnode[(s*384 + 128 + k)*L_ + n];
    }
    g_Wt[mat*16384 + n*128 + k] = __uint_as_float(f2tf32(v));
}

// A = x@W1, C = x@W2 (exact fp32), grid 64 x 256
__global__ void k_AC(const float* __restrict__ x, const float* __restrict__ W1,
                     const float* __restrict__ W2){
    __shared__ float xs[8][128];
    int r0 = blockIdx.x * 8;
    int tid = threadIdx.x;
    for (int i = tid; i < 1024; i += 256) xs[i>>7][i&127] = x[(r0 + (i>>7))*128 + (i&127)];
    __syncthreads();
    int c = tid & 127, rq = tid >> 7;
    float a1[4] = {0,0,0,0}, a2[4] = {0,0,0,0};
    for (int k = 0; k < 128; k++){
        float w1 = W1[k*128 + c], w2 = W2[k*128 + c];
        #pragma unroll
        for (int j = 0; j < 4; j++){
            float xv = xs[rq*4 + j][k];
            a1[j] += xv*w1; a2[j] += xv*w2;
        }
    }
    #pragma unroll
    for (int j = 0; j < 4; j++){
        g_A[(r0 + rq*4 + j)*128 + c] = a1[j];
        g_C[(r0 + rq*4 + j)*128 + c] = a2[j];
    }
}

// eenc = lrelu(edge_attr @ Wenc + b) via mma, grid 16
#define SMEM_EENC ((16896 + 8704) * 4)
__global__ __launch_bounds__(256, 1) void k_eenc(const float* __restrict__ ea,
                                                 const float* __restrict__ bias){
    extern __shared__ float sm[];
    float* s_x = sm;
    float* s_w = sm + 16896;
    int tid = threadIdx.x, wid = tid >> 5, lane = tid & 31;
    int row0 = blockIdx.x * 128;
    int trow = lane >> 2, tcol2 = (lane & 3)*2;
    int r128 = (wid & 3)*32, n128 = (wid >> 2)*64;

    #pragma unroll 4
    for (int i = tid; i < 4096; i += 256){
        int row = i >> 5, c4 = i & 31;
        *(float4*)&s_x[row*PITCH + c4*4] = *(const float4*)&ea[(row0+row)*128 + c4*4];
    }
    uint32_t xb = smem_u32(s_x), wsb = smem_u32(s_w);
    uint32_t aA[2], aB[4];
    #pragma unroll
    for (int m = 0; m < 2; m++){
        int r = r128 + m*16 + ((lane>>3)&1)*8 + (lane&7);
        aA[m] = xb + (uint32_t)(r*PITCH + ((lane>>4)<<2))*4u;
    }
    #pragma unroll
    for (int p = 0; p < 4; p++){
        int r = n128 + p*16 + ((lane>>4)<<3) + (lane&7);
        aB[p] = wsb + (uint32_t)(r*WPITCH + (((lane>>3)&1)<<2))*4u;
    }
    float c8[2][8][4];
    #pragma unroll
    for (int m=0;m<2;m++) for (int nt=0;nt<8;nt++) for (int q=0;q<4;q++) c8[m][nt][q]=0.f;

    load_wchunk(s_w, g_Wt, 0, tid);
    __syncthreads();
    gemm128_chunk(c8, aA, aB, 0);
    __syncthreads();
    load_wchunk(s_w, g_Wt, 64, tid);
    __syncthreads();
    gemm128_chunk(c8, aA, aB, 64);

    #pragma unroll
    for (int m = 0; m < 2; m++){
        int rA = row0 + r128 + m*16 + trow;
        #pragma unroll
        for (int nt = 0; nt < 8; nt++){
            int col = n128 + nt*8 + tcol2;
            float2 bi = *(const float2*)&bias[col];
            *(float2*)&g_eenc[rA*128 + col] =
                make_float2(lrelu(c8[m][nt][0]+bi.x), lrelu(c8[m][nt][1]+bi.y));
            *(float2*)&g_eenc[(rA+8)*128 + col] =
                make_float2(lrelu(c8[m][nt][2]+bi.x), lrelu(c8[m][nt][3]+bi.y));
        }
    }
}

// ---------------- fused per-(b,d) kernel ----------------
// SMEM float layout
#define O_X    0        // 128*132 = 16896
#define O_W    16896    // 128*68  = 8704
#define O_H    25600    // 64*132  = 8448
#define O_HS   34048    // 64*132  (aliased by agg)
#define O_HD   42496    // 64*132
#define O_GV   50944    // 256 (gve | gvn)
#define O_WSC  51200    // 128
#define O_SC   51328    // 256
#define O_INT  51584    // ints: src 256, dst 256, coff 65, cedge 256 (+pad)
#define SMEM_FUSED ((51584 + 840) * 4)

__global__ __launch_bounds__(256, 1) void k_fused(
    const float* __restrict__ spdist, const int* __restrict__ edge_index,
    const float* __restrict__ w3, const float* __restrict__ bias,
    const float* __restrict__ Wsc, const float* __restrict__ bsc,
    float* __restrict__ out)
{
    extern __shared__ float sm[];
    float* s_x   = sm + O_X;
    float* s_w   = sm + O_W;
    float* s_h   = sm + O_H;
    float* s_hs  = sm + O_HS;     // also agg
    float* s_hd  = sm + O_HD;
    float* s_gv  = sm + O_GV;
    float* s_wsc = sm + O_WSC;
    float* s_sc  = sm + O_SC;
    int*   s_src = (int*)(sm + O_INT);
    int*   s_dst = s_src + 256;
    int*   s_coff = s_dst + 256;
    int*   s_cedge = s_coff + 66;

    int tid = threadIdx.x, wid = tid >> 5, lane = tid & 31;
    int bd = blockIdx.x, b = bd >> 6, d = bd & 63;
    int trow = lane >> 2, tcol2 = (lane & 3)*2;
    int r128 = (wid & 3)*32, n128 = (wid >> 2)*64;
    int r64  = (wid & 1)*32, n64  = (wid >> 1)*32;
    float bsc0 = bsc[0];

    // init loads
    if (tid < 256){
        s_src[tid] = edge_index[b*512 + tid];
        s_dst[tid] = edge_index[b*512 + 256 + tid];
        s_cedge[tid] = g_csr_edge[b*256 + tid];
    }
    if (tid < 128) s_wsc[tid] = Wsc[tid];
    if (tid < 65)  s_coff[tid] = g_csr_off[b*65 + tid];

    // h0 = lrelu(A[b,i] + C[bd] + sp*w3 + bias)
    #pragma unroll
    for (int i = tid; i < 2048; i += 256){
        int row = i >> 5, c4 = i & 31;
        float sp = spdist[(b*64 + d)*64 + row];
        float4 a  = *(const float4*)&g_A[(b*64 + row)*128 + c4*4];
        float4 cc = *(const float4*)&g_C[bd*128 + c4*4];
        float4 w  = *(const float4*)&w3[c4*4];
        float4 bi = *(const float4*)&bias[c4*4];
        float4 o;
        o.x = lrelu(a.x + cc.x + sp*w.x + bi.x);
        o.y = lrelu(a.y + cc.y + sp*w.y + bi.y);
        o.z = lrelu(a.z + cc.z + sp*w.z + bi.z);
        o.w = lrelu(a.w + cc.w + sp*w.w + bi.w);
        *(float4*)&s_h[row*PITCH + c4*4] = o;
    }

    // fragment base addresses
    uint32_t xb = smem_u32(s_x), hb = smem_u32(s_h), gb = smem_u32(s_hs), wsb = smem_u32(s_w);
    uint32_t aAx[2], aAh[2], aAg[2], aB128[4], aB64[2];
    #pragma unroll
    for (int m = 0; m < 2; m++){
        int off = ((lane>>4)<<2);
        int rx = r128 + m*16 + ((lane>>3)&1)*8 + (lane&7);
        int rh = r64  + m*16 + ((lane>>3)&1)*8 + (lane&7);
        aAx[m] = xb + (uint32_t)(rx*PITCH + off)*4u;
        aAh[m] = hb + (uint32_t)(rh*PITCH + off)*4u;
        aAg[m] = gb + (uint32_t)(rh*PITCH + off)*4u;
    }
    #pragma unroll
    for (int p = 0; p < 4; p++){
        int r = n128 + p*16 + ((lane>>4)<<3) + (lane&7);
        aB128[p] = wsb + (uint32_t)(r*WPITCH + (((lane>>3)&1)<<2))*4u;
    }
    #pragma unroll
    for (int p = 0; p < 2; p++){
        int r = n64 + p*16 + ((lane>>4)<<3) + (lane&7);
        aB64[p] = wsb + (uint32_t)(r*WPITCH + (((lane>>3)&1)<<2))*4u;
    }

    for (int s = 0; s < 2; s++){
        const float* Wbase = g_Wt + (1 + s*5)*16384;
        // step preamble
        if (tid < 128) s_gv[tid] = g_gve[(s*8 + b)*128 + tid];
        else if (s == 0) s_gv[tid] = g_gvn[b*128 + (tid - 128)];
        if (s == 1 && tid < 256) s_sc[tid] = bsc0;

        // ---- hs = h@Ws ; hd = h@Wd ----
        for (int which = 0; which < 2; which++){
            const float* W = Wbase + (1 + which)*16384;
            float c6[2][4][4];
            #pragma unroll
            for (int m=0;m<2;m++) for (int nt=0;nt<4;nt++) for (int q=0;q<4;q++) c6[m][nt][q]=0.f;
            __syncthreads();
            load_wchunk(s_w, W, 0, tid);
            __syncthreads();
            gemm64_chunk(c6, aAh, aB64, 0);
            __syncthreads();
            load_wchunk(s_w, W, 64, tid);
            __syncthreads();
            gemm64_chunk(c6, aAh, aB64, 64);
            float* dstb = which ? s_hd : s_hs;
            #pragma unroll
            for (int m = 0; m < 2; m++){
                int rA = r64 + m*16 + trow;
                #pragma unroll
                for (int nt = 0; nt < 4; nt++){
                    int col = n64 + nt*8 + tcol2;
                    *(float2*)&dstb[rA*PITCH + col]     = make_float2(c6[m][nt][0], c6[m][nt][1]);
                    *(float2*)&dstb[(rA+8)*PITCH + col] = make_float2(c6[m][nt][2], c6[m][nt][3]);
                }
            }
        }

        // ---- edge tiles ----
        float part[2][2];
        for (int et = 0; et < 2; et++){
            int e0 = et*128;
            __syncthreads();   // s_x / s_w free; hd stores visible
            const float* Xsrc = (s == 0) ? (g_eenc + (b*256 + e0)*128)
                                         : (g_ee + (bd*256 + e0)*128);
            #pragma unroll 4
            for (int i = tid; i < 4096; i += 256){
                int row = i >> 5, c4 = i & 31;
                *(float4*)&s_x[row*PITCH + c4*4] = *(const float4*)&Xsrc[row*128 + c4*4];
            }
            load_wchunk(s_w, Wbase, 0, tid);
            float c8[2][8][4];
            #pragma unroll
            for (int m=0;m<2;m++) for (int nt=0;nt<8;nt++) for (int q=0;q<4;q++) c8[m][nt][q]=0.f;
            __syncthreads();
            gemm128_chunk(c8, aAx, aB128, 0);
            __syncthreads();
            load_wchunk(s_w, Wbase, 64, tid);
            __syncthreads();
            gemm128_chunk(c8, aAx, aB128, 64);
            __syncthreads();

            if (s == 0){
                float* eeout = g_ee + (bd*256 + e0)*128;
                #pragma unroll
                for (int m = 0; m < 2; m++){
                    int lrA = r128 + m*16 + trow, lrB = lrA + 8;
                    int sA = s_src[e0+lrA], dA = s_dst[e0+lrA];
                    int sB = s_src[e0+lrB], dB = s_dst[e0+lrB];
                    #pragma unroll
                    for (int nt = 0; nt < 8; nt++){
                        int col = n128 + nt*8 + tcol2;
                        float2 gv = *(float2*)&s_gv[col];
                        float2 h1 = *(float2*)&s_hs[sA*PITCH + col];
                        float2 d1 = *(float2*)&s_hd[dA*PITCH + col];
                        float2 p1 = *(float2*)&s_x[lrA*PITCH + col];
                        *(float2*)&eeout[lrA*128 + col] = make_float2(
                            p1.x + lrelu(c8[m][nt][0] + h1.x + d1.x + gv.x),
                            p1.y + lrelu(c8[m][nt][1] + h1.y + d1.y + gv.y));
                        float2 h2 = *(float2*)&s_hs[sB*PITCH + col];
                        float2 d2 = *(float2*)&s_hd[dB*PITCH + col];
                        float2 p2 = *(float2*)&s_x[lrB*PITCH + col];
                        *(float2*)&eeout[lrB*128 + col] = make_float2(
                            p2.x + lrelu(c8[m][nt][2] + h2.x + d2.x + gv.x),
                            p2.y + lrelu(c8[m][nt][3] + h2.y + d2.y + gv.y));
                    }
                }
            } else {
                part[0][0]=part[0][1]=part[1][0]=part[1][1]=0.f;
                #pragma unroll
                for (int m = 0; m < 2; m++){
                    int lrA = r128 + m*16 + trow, lrB = lrA + 8;
                    int sA = s_src[e0+lrA], dA = s_dst[e0+lrA];
                    int sB = s_src[e0+lrB], dB = s_dst[e0+lrB];
                    #pragma unroll
                    for (int nt = 0; nt < 8; nt++){
                        int col = n128 + nt*8 + tcol2;
                        float2 gv = *(float2*)&s_gv[col];
                        float2 wv = *(float2*)&s_wsc[col];
                        float2 h1 = *(float2*)&s_hs[sA*PITCH + col];
                        float2 d1 = *(float2*)&s_hd[dA*PITCH + col];
                        float2 p1 = *(float2*)&s_x[lrA*PITCH + col];
                        float o1x = p1.x + lrelu(c8[m][nt][0] + h1.x + d1.x + gv.x);
                        float o1y = p1.y + lrelu(c8[m][nt][1] + h1.y + d1.y + gv.y);
                        part[m][0] += o1x*wv.x + o1y*wv.y;
                        float2 h2 = *(float2*)&s_hs[sB*PITCH + col];
                        float2 d2 = *(float2*)&s_hd[dB*PITCH + col];
                        float2 p2 = *(float2*)&s_x[lrB*PITCH + col];
                        float o2x = p2.x + lrelu(c8[m][nt][2] + h2.x + d2.x + gv.x);
                        float o2y = p2.y + lrelu(c8[m][nt][3] + h2.y + d2.y + gv.y);
                        part[m][1] += o2x*wv.x + o2y*wv.y;
                    }
                }
                #pragma unroll
                for (int m = 0; m < 2; m++)
                    #pragma unroll
                    for (int i = 0; i < 2; i++){
                        float v = part[m][i];
                        v += __shfl_xor_sync(0xFFFFFFFFu, v, 1);
                        v += __shfl_xor_sync(0xFFFFFFFFu, v, 2);
                        if ((lane & 3) == 0)
                            atomicAdd(&s_sc[e0 + r128 + m*16 + trow + i*8], v);
                    }
            }
        }

        if (s == 0){
            // ---- agg (from g_ee, CSR) into s_hs (hs now dead) ----
            __syncthreads();
            #pragma unroll
            for (int it = 0; it < 2; it++){
                int idx = tid + it*256;
                int n = idx >> 3, cg = idx & 7;
                float acc[16];
                #pragma unroll
                for (int q = 0; q < 16; q++) acc[q] = 0.f;
                int j0 = s_coff[n], j1 = s_coff[n+1];
                const float* eb = g_ee + bd*256*128 + cg*16;
                for (int j = j0; j < j1; j++){
                    const float* p = eb + s_cedge[j]*128;
                    #pragma unroll
                    for (int q = 0; q < 4; q++){
                        float4 v = *(const float4*)&p[q*4];
                        acc[q*4]   += v.x; acc[q*4+1] += v.y;
                        acc[q*4+2] += v.z; acc[q*4+3] += v.w;
                    }
                }
                #pragma unroll
                for (int q = 0; q < 4; q++)
                    *(float4*)&s_hs[n*PITCH + cg*16 + q*4] =
                        make_float4(acc[q*4], acc[q*4+1], acc[q*4+2], acc[q*4+3]);
            }

            // ---- node update: h += lrelu(h@Wn1 + agg@Wn2 + gvn) ----
            float c6[2][4][4];
            #pragma unroll
            for (int m=0;m<2;m++) for (int nt=0;nt<4;nt++) for (int q=0;q<4;q++) c6[m][nt][q]=0.f;
            const float* Wn1 = Wbase + 3*16384;
            const float* Wn2 = Wbase + 4*16384;
            __syncthreads();
            load_wchunk(s_w, Wn1, 0, tid);
            __syncthreads();
            gemm64_chunk(c6, aAh, aB64, 0);
            __syncthreads();
            load_wchunk(s_w, Wn1, 64, tid);
            __syncthreads();
            gemm64_chunk(c6, aAh, aB64, 64);
            __syncthreads();
            load_wchunk(s_w, Wn2, 0, tid);
            __syncthreads();
            gemm64_chunk(c6, aAg, aB64, 0);
            __syncthreads();
            load_wchunk(s_w, Wn2, 64, tid);
            __syncthreads();
            gemm64_chunk(c6, aAg, aB64, 64);
            __syncthreads();   // all reads of s_h done
            #pragma unroll
            for (int m = 0; m < 2; m++){
                int rA = r64 + m*16 + trow;
                #pragma unroll
                for (int nt = 0; nt < 4; nt++){
                    int col = n64 + nt*8 + tcol2;
                    float2 gv = *(float2*)&s_gv[128 + col];
                    float2 h1 = *(float2*)&s_h[rA*PITCH + col];
                    float2 h2 = *(float2*)&s_h[(rA+8)*PITCH + col];
                    h1.x += lrelu(c6[m][nt][0] + gv.x);
                    h1.y += lrelu(c6[m][nt][1] + gv.y);
                    h2.x += lrelu(c6[m][nt][2] + gv.x);
                    h2.y += lrelu(c6[m][nt][3] + gv.y);
                    *(float2*)&s_h[rA*PITCH + col]     = h1;
                    *(float2*)&s_h[(rA+8)*PITCH + col] = h2;
                }
            }
            __syncthreads();
        } else {
            __syncthreads();
            if (tid < 256)
                out[b*(E_*N_) + tid*N_ + d] = s_sc[tid];
        }
    }
}

// ---------------- launch ----------------
extern "C" void kernel_launch(void* const* d_in, const int* in_sizes, int n_in,
                              void* d_out, int out_size){
    const float* x          = (const float*)d_in[0];
    const float* edge_attr  = (const float*)d_in[1];
    const float* u          = (const float*)d_in[2];
    const float* spdist     = (const float*)d_in[3];
    const int*   edge_index = (const int*)  d_in[4];
    const float* W_node_enc = (const float*)d_in[5];
    const float* b_node_enc = (const float*)d_in[6];
    const float* W_edge_enc = (const float*)d_in[7];
    const float* b_edge_enc = (const float*)d_in[8];
    const float* W_glob_enc = (const float*)d_in[9];
    const float* b_glob_enc = (const float*)d_in[10];
    const float* W_edge_upd = (const float*)d_in[11];
    const float* b_edge_upd = (const float*)d_in[12];
    const float* W_node_upd = (const float*)d_in[13];
    const float* b_node_upd = (const float*)d_in[14];
    const float* W_score    = (const float*)d_in[15];
    const float* b_score    = (const float*)d_in[16];
    float* out = (float*)d_out;

    static int inited = 0;
    if (!inited){
        cudaFuncSetAttribute(k_eenc,  cudaFuncAttributeMaxDynamicSharedMemorySize, SMEM_EENC);
        cudaFuncSetAttribute(k_fused, cudaFuncAttributeMaxDynamicSharedMemorySize, SMEM_FUSED);
        inited = 1;
    }

    k_gg   <<<B_, L_>>>(u, W_glob_enc, b_glob_enc);
    k_gvec <<<2*2*B_, L_>>>(W_edge_upd, b_edge_upd, W_node_upd, b_node_upd);
    k_wprep<<<11*16384/256, 256>>>(W_edge_enc, W_edge_upd, W_node_upd);
    k_csr  <<<1, 32>>>(edge_index);
    k_AC   <<<64, 256>>>(x, W_node_enc, W_node_enc + 128*128);
    k_eenc <<<16, 256, SMEM_EENC>>>(edge_attr, b_edge_enc);
    k_fused<<<512, 256, SMEM_FUSED>>>(spdist, edge_index,
                                      W_node_enc + 256*128, b_node_enc,
                                      W_score, b_score, out);
}

// round 6
// speedup vs baseline: 2.8431x; 1.2145x over previous
#include <cuda_runtime.h>
#include <cstdint>

#define B_   8
#define N_   64
#define E_   256
#define L_   128
#define PITCH  132
#define WPITCH 68

// ---------------- device globals ----------------
__device__ float g_A   [512*128];
__device__ float g_C   [512*128];
__device__ float g_eenc[2048*128];
__device__ float g_gve [2*8*128];
__device__ float g_gvn [2*8*128];
__device__ float g_ee  [512*256*128];
__device__ float g_Wt  [11*128*128];
__device__ int   g_csr_off [8*65];
__device__ int   g_csr_edge[8*256];

__device__ __forceinline__ float lrelu(float v){ return v > 0.f ? v : 0.01f*v; }
__device__ __forceinline__ uint32_t smem_u32(const void* p){
    uint32_t a;
    asm("{ .reg .u64 t; cvta.to.shared.u64 t, %1; cvt.u32.u64 %0, t; }" : "=r"(a) : "l"(p));
    return a;
}
__device__ __forceinline__ float f2tf32f(float f){
    uint32_t r; asm("cvt.rna.tf32.f32 %0, %1;" : "=r"(r) : "f"(f));
    return __uint_as_float(r);
}
__device__ __forceinline__ uint32_t tf32r(uint32_t x){
    uint32_t r; asm("cvt.rna.tf32.f32 %0, %1;" : "=r"(r) : "f"(__uint_as_float(x))); return r;
}

#define LDSM4(D, addr) \
    asm volatile("ldmatrix.sync.aligned.m8n8.x4.shared.b16 {%0,%1,%2,%3}, [%4];" \
        : "=r"((D)[0]),"=r"((D)[1]),"=r"((D)[2]),"=r"((D)[3]) : "r"(addr))

#define MMA_T(C, A, b0, b1) \
    asm volatile("mma.sync.aligned.m16n8k8.row.col.f32.tf32.tf32.f32 " \
        "{%0,%1,%2,%3}, {%4,%5,%6,%7}, {%8,%9}, {%0,%1,%2,%3};" \
        : "+f"((C)[0]),"+f"((C)[1]),"+f"((C)[2]),"+f"((C)[3]) \
        : "r"((A)[0]),"r"((A)[1]),"r"((A)[2]),"r"((A)[3]), "r"(b0),"r"(b1))

#define LDA_CVT(A, addr) do { LDSM4(A, addr); \
    (A)[0]=tf32r((A)[0]); (A)[1]=tf32r((A)[1]); (A)[2]=tf32r((A)[2]); (A)[3]=tf32r((A)[3]); } while(0)

// ---------------- gemm building blocks ----------------
// weight chunk load: s [128n x 64k+pad] <- Wmat[n][kc..kc+63]
template<int NT>
__device__ __forceinline__ void load_wchunk(float* s_w, const float* __restrict__ Wmat,
                                            int kc, int tid){
    const float* Wp = Wmat + kc;
    #pragma unroll
    for (int i = tid; i < 2048; i += NT){
        int n = i >> 4, k4 = i & 15;
        *(float4*)&s_w[n*WPITCH + k4*4] = *(const float4*)&Wp[n*128 + k4*4];
    }
}

// 16-warp 128x128: 2 B frags per warp
__device__ __forceinline__ void g128x16(float c[2][4][4], const uint32_t aA[2],
                                        const uint32_t aB[2], int kc){
    #pragma unroll
    for (int k = 0; k < 8; k++){
        uint32_t A[2][4];
        #pragma unroll
        for (int m = 0; m < 2; m++) LDA_CVT(A[m], aA[m] + (uint32_t)(kc + k*8)*4u);
        #pragma unroll
        for (int p = 0; p < 2; p++){
            uint32_t Bv[4];
            LDSM4(Bv, aB[p] + (uint32_t)k*32u);
            #pragma unroll
            for (int m = 0; m < 2; m++){
                MMA_T(c[m][2*p],   A[m], Bv[0], Bv[1]);
                MMA_T(c[m][2*p+1], A[m], Bv[2], Bv[3]);
            }
        }
    }
}

// 16-warp 64x128: 1 B frag per warp
__device__ __forceinline__ void g64x16(float c[2][2][4], const uint32_t aA[2],
                                       uint32_t aB, int kc){
    #pragma unroll
    for (int k = 0; k < 8; k++){
        uint32_t A[2][4];
        #pragma unroll
        for (int m = 0; m < 2; m++) LDA_CVT(A[m], aA[m] + (uint32_t)(kc + k*8)*4u);
        uint32_t Bv[4];
        LDSM4(Bv, aB + (uint32_t)k*32u);
        #pragma unroll
        for (int m = 0; m < 2; m++){
            MMA_T(c[m][0], A[m], Bv[0], Bv[1]);
            MMA_T(c[m][1], A[m], Bv[2], Bv[3]);
        }
    }
}

// 8-warp 128x128 (eenc): 4 B frags per warp
__device__ __forceinline__ void g128x8(float c[2][8][4], const uint32_t aA[2],
                                       const uint32_t aB[4], int kc){
    #pragma unroll
    for (int k = 0; k < 8; k++){
        uint32_t A[2][4];
        #pragma unroll
        for (int m = 0; m < 2; m++) LDA_CVT(A[m], aA[m] + (uint32_t)(kc + k*8)*4u);
        #pragma unroll
        for (int p = 0; p < 4; p++){
            uint32_t Bv[4];
            LDSM4(Bv, aB[p] + (uint32_t)k*32u);
            #pragma unroll
            for (int m = 0; m < 2; m++){
                MMA_T(c[m][2*p],   A[m], Bv[0], Bv[1]);
                MMA_T(c[m][2*p+1], A[m], Bv[2], Bv[3]);
            }
        }
    }
}

// ---------------- merged prep kernel ----------------
// blocks [0,640): wprep mats 1..10 ; [640,704): A/C gemm ; [704,712): csr ; [712,744): gvec
__global__ void k_prep(const float* __restrict__ x, const float* __restrict__ Wne,
                       const float* __restrict__ u, const float* __restrict__ Wg,
                       const float* __restrict__ bg,
                       const float* __restrict__ Wedge, const float* __restrict__ be,
                       const float* __restrict__ Wnode, const float* __restrict__ bn,
                       const int* __restrict__ edge_index){
    int blk = blockIdx.x, tid = threadIdx.x;
    if (blk < 640){
        // transpose + tf32-round weights: g_Wt[mat][n][k]
        int gi = blk*256 + tid;
        int mat = 1 + (gi >> 14);
        int el = gi & 16383;
        int n = el >> 7, k = el & 127;
        int m = mat - 1, s = m / 5, t = m % 5;
        float v;
        if      (t == 0) v = Wedge[(s*512 +       k)*L_ + n];
        else if (t == 1) v = Wedge[(s*512 + 128 + k)*L_ + n];
        else if (t == 2) v = Wedge[(s*512 + 256 + k)*L_ + n];
        else if (t == 3) v = Wnode[(s*384 +       k)*L_ + n];
        else             v = Wnode[(s*384 + 128 + k)*L_ + n];
        g_Wt[mat*16384 + n*128 + k] = f2tf32f(v);
    } else if (blk < 704){
        // A = x@W1, C = x@W2 (exact fp32)
        __shared__ float xs[8][128];
        const float* W1 = Wne;
        const float* W2 = Wne + 16384;
        int r0 = (blk - 640)*8;
        for (int i = tid; i < 1024; i += 256) xs[i>>7][i&127] = x[(r0 + (i>>7))*128 + (i&127)];
        __syncthreads();
        int c = tid & 127, rq = tid >> 7;
        float a1[4] = {0,0,0,0}, a2[4] = {0,0,0,0};
        for (int k = 0; k < 128; k++){
            float w1 = W1[k*128 + c], w2 = W2[k*128 + c];
            #pragma unroll
            for (int j = 0; j < 4; j++){
                float xv = xs[rq*4 + j][k];
                a1[j] += xv*w1; a2[j] += xv*w2;
            }
        }
        #pragma unroll
        for (int j = 0; j < 4; j++){
            g_A[(r0 + rq*4 + j)*128 + c] = a1[j];
            g_C[(r0 + rq*4 + j)*128 + c] = a2[j];
        }
    } else if (blk < 712){
        // per-graph CSR by destination
        __shared__ int cnt[64], off[66];
        int b = blk - 704;
        if (tid < 64) cnt[tid] = 0;
        __syncthreads();
        int dv = edge_index[b*512 + 256 + tid];
        atomicAdd(&cnt[dv], 1);
        __syncthreads();
        if (tid == 0){
            int o = 0;
            for (int n = 0; n < 64; n++){ off[n] = o; o += cnt[n]; }
            off[64] = o;
            for (int n = 0; n <= 64; n++) g_csr_off[b*65 + n] = off[n];
            for (int n = 0; n < 64; n++) cnt[n] = off[n];
        }
        __syncthreads();
        int pos = atomicAdd(&cnt[dv], 1);
        g_csr_edge[b*256 + pos] = tid;
    } else {
        // gvec with gg recomputed locally
        __shared__ float sgg[128];
        int id = blk - 712;
        int b = id & 7, s = (id >> 3) & 1, kind = id >> 4;
        if (tid < 128){
            float acc = bg[tid];
            #pragma unroll 8
            for (int k = 0; k < 128; k++) acc += u[b*128 + k] * Wg[k*128 + tid];
            sgg[tid] = lrelu(acc);
        }
        __syncthreads();
        if (tid < 128){
            if (kind == 0){
                const float* W = Wedge + (s*512 + 384)*L_;
                float acc = be[s*128 + tid];
                #pragma unroll 8
                for (int k = 0; k < 128; k++) acc += sgg[k] * W[k*128 + tid];
                g_gve[(s*8 + b)*128 + tid] = acc;
            } else {
                const float* W = Wnode + (s*384 + 256)*L_;
                float acc = bn[s*128 + tid];
                #pragma unroll 8
                for (int k = 0; k < 128; k++) acc += sgg[k] * W[k*128 + tid];
                g_gvn[(s*8 + b)*128 + tid] = acc;
            }
        }
    }
}

// ---------------- edge encoder (self-contained) ----------------
#define SMEM_EENC ((16896 + 8704 + 8704) * 4)
__global__ __launch_bounds__(256, 1) void k_eenc(const float* __restrict__ ea,
                                                 const float* __restrict__ Wenc,
                                                 const float* __restrict__ bias){
    extern __shared__ float sm[];
    float* s_x  = sm;
    float* s_w  = sm + 16896;
    float* s_w2 = sm + 25600;
    int tid = threadIdx.x, wid = tid >> 5, lane = tid & 31;
    int row0 = blockIdx.x * 128;
    int trow = lane >> 2, tcol2 = (lane & 3)*2;
    int r128 = (wid & 3)*32, n128 = (wid >> 2)*64;

    #pragma unroll 4
    for (int i = tid; i < 4096; i += 256){
        int row = i >> 5, c4 = i & 31;
        *(float4*)&s_x[row*PITCH + c4*4] = *(const float4*)&ea[(row0+row)*128 + c4*4];
    }
    // transpose weight [k][n] -> [n][k], tf32-rounded, split into 2 k-chunks
    for (int i = tid; i < 16384; i += 256){
        int k = i >> 7, n = i & 127;
        float v = f2tf32f(Wenc[k*128 + n]);
        if (k < 64) s_w [n*WPITCH + k]      = v;
        else        s_w2[n*WPITCH + k - 64] = v;
    }
    __syncthreads();

    uint32_t xb = smem_u32(s_x), wb1 = smem_u32(s_w), wb2 = smem_u32(s_w2);
    uint32_t aA[2], aB[4], aB2[4];
    #pragma unroll
    for (int m = 0; m < 2; m++){
        int r = r128 + m*16 + ((lane>>3)&1)*8 + (lane&7);
        aA[m] = xb + (uint32_t)(r*PITCH + ((lane>>4)<<2))*4u;
    }
    #pragma unroll
    for (int p = 0; p < 4; p++){
        int r = n128 + p*16 + ((lane>>4)<<3) + (lane&7);
        uint32_t off = (uint32_t)(r*WPITCH + (((lane>>3)&1)<<2))*4u;
        aB[p] = wb1 + off; aB2[p] = wb2 + off;
    }
    float c8[2][8][4];
    #pragma unroll
    for (int m=0;m<2;m++) for (int nt=0;nt<8;nt++) for (int q=0;q<4;q++) c8[m][nt][q]=0.f;
    g128x8(c8, aA, aB, 0);
    g128x8(c8, aA, aB2, 64);

    #pragma unroll
    for (int m = 0; m < 2; m++){
        int rA = row0 + r128 + m*16 + trow;
        #pragma unroll
        for (int nt = 0; nt < 8; nt++){
            int col = n128 + nt*8 + tcol2;
            float2 bi = *(const float2*)&bias[col];
            *(float2*)&g_eenc[rA*128 + col] =
                make_float2(lrelu(c8[m][nt][0]+bi.x), lrelu(c8[m][nt][1]+bi.y));
            *(float2*)&g_eenc[(rA+8)*128 + col] =
                make_float2(lrelu(c8[m][nt][2]+bi.x), lrelu(c8[m][nt][3]+bi.y));
        }
    }
}

// ---------------- fused per-(b,d) kernel, 512 threads ----------------
#define O_X    0        // 128*132 = 16896 (edge tile / spare weight buffer)
#define O_W    16896    // 8704
#define O_H    25600    // 64*132 = 8448
#define O_HS   34048    // 8448 (aliased by agg)
#define O_HD   42496    // 8448
#define O_GV   50944    // 256
#define O_WSC  51200    // 128
#define O_SC   51328    // 256
#define O_INT  51584
#define SMEM_FUSED ((51584 + 840) * 4)

__global__ __launch_bounds__(512, 1) void k_fused(
    const float* __restrict__ spdist, const int* __restrict__ edge_index,
    const float* __restrict__ w3, const float* __restrict__ bias,
    const float* __restrict__ Wsc, const float* __restrict__ bsc,
    float* __restrict__ out)
{
    extern __shared__ float sm[];
    float* s_x   = sm + O_X;
    float* s_w   = sm + O_W;
    float* s_h   = sm + O_H;
    float* s_hs  = sm + O_HS;
    float* s_hd  = sm + O_HD;
    float* s_gv  = sm + O_GV;
    float* s_wsc = sm + O_WSC;
    float* s_sc  = sm + O_SC;
    int*   s_src = (int*)(sm + O_INT);
    int*   s_dst = s_src + 256;
    int*   s_coff = s_dst + 256;
    int*   s_cedge = s_coff + 66;

    int tid = threadIdx.x, wid = tid >> 5, lane = tid & 31;
    int bd = blockIdx.x, b = bd >> 6, d = bd & 63;
    int trow = lane >> 2, tcol2 = (lane & 3)*2;
    int wr  = (wid & 3)*32, wn  = (wid >> 2)*32;   // 128-gemm layout
    int wr2 = (wid & 1)*32, wn2 = (wid >> 1)*16;   // 64-gemm layout
    float bsc0 = bsc[0];

    if (tid < 256){
        s_src[tid] = edge_index[b*512 + tid];
        s_dst[tid] = edge_index[b*512 + 256 + tid];
        s_cedge[tid] = g_csr_edge[b*256 + tid];
    }
    if (tid < 128) s_wsc[tid] = Wsc[tid];
    if (tid < 65)  s_coff[tid] = g_csr_off[b*65 + tid];

    // h0 = lrelu(A[b,i] + C[bd] + sp*w3 + bias)
    #pragma unroll
    for (int i = tid; i < 2048; i += 512){
        int row = i >> 5, c4 = i & 31;
        float sp = spdist[(b*64 + d)*64 + row];
        float4 a  = *(const float4*)&g_A[(b*64 + row)*128 + c4*4];
        float4 cc = *(const float4*)&g_C[bd*128 + c4*4];
        float4 w  = *(const float4*)&w3[c4*4];
        float4 bi = *(const float4*)&bias[c4*4];
        float4 o;
        o.x = lrelu(a.x + cc.x + sp*w.x + bi.x);
        o.y = lrelu(a.y + cc.y + sp*w.y + bi.y);
        o.z = lrelu(a.z + cc.z + sp*w.z + bi.z);
        o.w = lrelu(a.w + cc.w + sp*w.w + bi.w);
        *(float4*)&s_h[row*PITCH + c4*4] = o;
    }

    // fragment addresses
    uint32_t xb = smem_u32(s_x), hb = smem_u32(s_h), gbm = smem_u32(s_hs), wsb = smem_u32(s_w);
    uint32_t aAx[2], aAh[2], aAg[2], aBw128[2];
    #pragma unroll
    for (int m = 0; m < 2; m++){
        int off = ((lane>>4)<<2);
        int rx = wr  + m*16 + ((lane>>3)&1)*8 + (lane&7);
        int rh = wr2 + m*16 + ((lane>>3)&1)*8 + (lane&7);
        aAx[m] = xb + (uint32_t)(rx*PITCH + off)*4u;
        aAh[m] = hb + (uint32_t)(rh*PITCH + off)*4u;
        aAg[m] = gbm + (uint32_t)(rh*PITCH + off)*4u;
    }
    #pragma unroll
    for (int p = 0; p < 2; p++){
        int r = wn + p*16 + ((lane>>4)<<3) + (lane&7);
        aBw128[p] = wsb + (uint32_t)(r*WPITCH + (((lane>>3)&1)<<2))*4u;
    }
    int nr2 = wn2 + ((lane>>4)<<3) + (lane&7);
    uint32_t kc4 = (uint32_t)((((lane>>3)&1)<<2));
    uint32_t aBw64 = wsb + (uint32_t)(nr2*WPITCH)*4u + kc4*4u;
    uint32_t aBx64 = xb  + (uint32_t)(nr2*WPITCH)*4u + kc4*4u;

    for (int s = 0; s < 2; s++){
        const float* Wbase = g_Wt + (1 + s*5)*16384;
        if (tid < 128) s_gv[tid] = g_gve[(s*8 + b)*128 + tid];
        else if (tid < 256 && s == 0) s_gv[tid] = g_gvn[b*128 + (tid - 128)];
        if (s == 1 && tid < 256) s_sc[tid] = bsc0;

        // ---- hs = h@Ws ; hd = h@Wd ---- (dual-buffer weight chunks: s_w + s_x)
        for (int which = 0; which < 2; which++){
            const float* W = Wbase + (1 + which)*16384;
            __syncthreads();
            load_wchunk<512>(s_w, W, 0, tid);
            load_wchunk<512>(s_x, W, 64, tid);
            float c6[2][2][4];
            #pragma unroll
            for (int m=0;m<2;m++) for (int nt=0;nt<2;nt++) for (int q=0;q<4;q++) c6[m][nt][q]=0.f;
            __syncthreads();
            g64x16(c6, aAh, aBw64, 0);
            g64x16(c6, aAh, aBx64, 64);
            float* dstb = which ? s_hd : s_hs;
            #pragma unroll
            for (int m = 0; m < 2; m++){
                int rA = wr2 + m*16 + trow;
                #pragma unroll
                for (int nt = 0; nt < 2; nt++){
                    int col = wn2 + nt*8 + tcol2;
                    *(float2*)&dstb[rA*PITCH + col]     = make_float2(c6[m][nt][0], c6[m][nt][1]);
                    *(float2*)&dstb[(rA+8)*PITCH + col] = make_float2(c6[m][nt][2], c6[m][nt][3]);
                }
            }
        }

        // ---- edge tiles ----
        for (int et = 0; et < 2; et++){
            int e0 = et*128;
            __syncthreads();
            const float* Xsrc = (s == 0) ? (g_eenc + (b*256 + e0)*128)
                                         : (g_ee + (bd*256 + e0)*128);
            #pragma unroll
            for (int i = tid; i < 4096; i += 512){
                int row = i >> 5, c4 = i & 31;
                *(float4*)&s_x[row*PITCH + c4*4] = *(const float4*)&Xsrc[row*128 + c4*4];
            }
            load_wchunk<512>(s_w, Wbase, 0, tid);
            float c8[2][4][4];
            #pragma unroll
            for (int m=0;m<2;m++) for (int nt=0;nt<4;nt++) for (int q=0;q<4;q++) c8[m][nt][q]=0.f;
            __syncthreads();
            g128x16(c8, aAx, aBw128, 0);
            __syncthreads();
            load_wchunk<512>(s_w, Wbase, 64, tid);
            __syncthreads();
            g128x16(c8, aAx, aBw128, 64);

            if (s == 0){
                float* eeout = g_ee + (bd*256 + e0)*128;
                #pragma unroll
                for (int m = 0; m < 2; m++){
                    int lrA = wr + m*16 + trow, lrB = lrA + 8;
                    int sA = s_src[e0+lrA], dA = s_dst[e0+lrA];
                    int sB = s_src[e0+lrB], dB = s_dst[e0+lrB];
                    #pragma unroll
                    for (int nt = 0; nt < 4; nt++){
                        int col = wn + nt*8 + tcol2;
                        float2 gv = *(float2*)&s_gv[col];
                        float2 h1 = *(float2*)&s_hs[sA*PITCH + col];
                        float2 d1 = *(float2*)&s_hd[dA*PITCH + col];
                        float2 p1 = *(float2*)&s_x[lrA*PITCH + col];
                        *(float2*)&eeout[lrA*128 + col] = make_float2(
                            p1.x + lrelu(c8[m][nt][0] + h1.x + d1.x + gv.x),
                            p1.y + lrelu(c8[m][nt][1] + h1.y + d1.y + gv.y));
                        float2 h2 = *(float2*)&s_hs[sB*PITCH + col];
                        float2 d2 = *(float2*)&s_hd[dB*PITCH + col];
                        float2 p2 = *(float2*)&s_x[lrB*PITCH + col];
                        *(float2*)&eeout[lrB*128 + col] = make_float2(
                            p2.x + lrelu(c8[m][nt][2] + h2.x + d2.x + gv.x),
                            p2.y + lrelu(c8[m][nt][3] + h2.y + d2.y + gv.y));
                    }
                }
            } else {
                float part[2][2];
                part[0][0]=part[0][1]=part[1][0]=part[1][1]=0.f;
                #pragma unroll
                for (int m = 0; m < 2; m++){
                    int lrA = wr + m*16 + trow, lrB = lrA + 8;
                    int sA = s_src[e0+lrA], dA = s_dst[e0+lrA];
                    int sB = s_src[e0+lrB], dB = s_dst[e0+lrB];
                    #pragma unroll
                    for (int nt = 0; nt < 4; nt++){
                        int col = wn + nt*8 + tcol2;
                        float2 gv = *(float2*)&s_gv[col];
                        float2 wv = *(float2*)&s_wsc[col];
                        float2 h1 = *(float2*)&s_hs[sA*PITCH + col];
                        float2 d1 = *(float2*)&s_hd[dA*PITCH + col];
                        float2 p1 = *(float2*)&s_x[lrA*PITCH + col];
                        float o1x = p1.x + lrelu(c8[m][nt][0] + h1.x + d1.x + gv.x);
                        float o1y = p1.y + lrelu(c8[m][nt][1] + h1.y + d1.y + gv.y);
                        part[m][0] += o1x*wv.x + o1y*wv.y;
                        float2 h2 = *(float2*)&s_hs[sB*PITCH + col];
                        float2 d2 = *(float2*)&s_hd[dB*PITCH + col];
                        float2 p2 = *(float2*)&s_x[lrB*PITCH + col];
                        float o2x = p2.x + lrelu(c8[m][nt][2] + h2.x + d2.x + gv.x);
                        float o2y = p2.y + lrelu(c8[m][nt][3] + h2.y + d2.y + gv.y);
                        part[m][1] += o2x*wv.x + o2y*wv.y;
                    }
                }
                #pragma unroll
                for (int m = 0; m < 2; m++)
                    #pragma unroll
                    for (int i = 0; i < 2; i++){
                        float v = part[m][i];
                        v += __shfl_xor_sync(0xFFFFFFFFu, v, 1);
                        v += __shfl_xor_sync(0xFFFFFFFFu, v, 2);
                        if ((lane & 3) == 0)
                            atomicAdd(&s_sc[e0 + wr + m*16 + trow + i*8], v);
                    }
            }
        }

        if (s == 0){
            // ---- agg from g_ee (CSR) into s_hs ----
            __syncthreads();
            {
                int n = tid >> 3, cg = tid & 7;
                float acc[16];
                #pragma unroll
                for (int q = 0; q < 16; q++) acc[q] = 0.f;
                int j0 = s_coff[n], j1 = s_coff[n+1];
                const float* eb = g_ee + bd*256*128 + cg*16;
                for (int j = j0; j < j1; j++){
                    const float* p = eb + s_cedge[j]*128;
                    #pragma unroll
                    for (int q = 0; q < 4; q++){
                        float4 v = *(const float4*)&p[q*4];
                        acc[q*4]   += v.x; acc[q*4+1] += v.y;
                        acc[q*4+2] += v.z; acc[q*4+3] += v.w;
                    }
                }
                // load node-update weight chunk pair while agg regs are live
                #pragma unroll
                for (int q = 0; q < 4; q++)
                    *(float4*)&s_hs[n*PITCH + cg*16 + q*4] =
                        make_float4(acc[q*4], acc[q*4+1], acc[q*4+2], acc[q*4+3]);
            }
            const float* Wn1 = Wbase + 3*16384;
            const float* Wn2 = Wbase + 4*16384;
            load_wchunk<512>(s_w, Wn1, 0, tid);
            load_wchunk<512>(s_x, Wn1, 64, tid);
            float c6[2][2][4];
            #pragma unroll
            for (int m=0;m<2;m++) for (int nt=0;nt<2;nt++) for (int q=0;q<4;q++) c6[m][nt][q]=0.f;
            __syncthreads();
            g64x16(c6, aAh, aBw64, 0);
            g64x16(c6, aAh, aBx64, 64);
            __syncthreads();
            load_wchunk<512>(s_w, Wn2, 0, tid);
            load_wchunk<512>(s_x, Wn2, 64, tid);
            __syncthreads();
            g64x16(c6, aAg, aBw64, 0);
            g64x16(c6, aAg, aBx64, 64);
            __syncthreads();      // all s_h reads done before update
            #pragma unroll
            for (int m = 0; m < 2; m++){
                int rA = wr2 + m*16 + trow;
                #pragma unroll
                for (int nt = 0; nt < 2; nt++){
                    int col = wn2 + nt*8 + tcol2;
                    float2 gv = *(float2*)&s_gv[128 + col];
                    float2 h1 = *(float2*)&s_h[rA*PITCH + col];
                    float2 h2 = *(float2*)&s_h[(rA+8)*PITCH + col];
                    h1.x += lrelu(c6[m][nt][0] + gv.x);
                    h1.y += lrelu(c6[m][nt][1] + gv.y);
                    h2.x += lrelu(c6[m][nt][2] + gv.x);
                    h2.y += lrelu(c6[m][nt][3] + gv.y);
                    *(float2*)&s_h[rA*PITCH + col]     = h1;
                    *(float2*)&s_h[(rA+8)*PITCH + col] = h2;
                }
            }
            __syncthreads();
        } else {
            __syncthreads();
            if (tid < 256)
                out[b*(E_*N_) + tid*N_ + d] = s_sc[tid];
        }
    }
}

// ---------------- launch ----------------
extern "C" void kernel_launch(void* const* d_in, const int* in_sizes, int n_in,
                              void* d_out, int out_size){
    const float* x          = (const float*)d_in[0];
    const float* edge_attr  = (const float*)d_in[1];
    const float* u          = (const float*)d_in[2];
    const float* spdist     = (const float*)d_in[3];
    const int*   edge_index = (const int*)  d_in[4];
    const float* W_node_enc = (const float*)d_in[5];
    const float* b_node_enc = (const float*)d_in[6];
    const float* W_edge_enc = (const float*)d_in[7];
    const float* b_edge_enc = (const float*)d_in[8];
    const float* W_glob_enc = (const float*)d_in[9];
    const float* b_glob_enc = (const float*)d_in[10];
    const float* W_edge_upd = (const float*)d_in[11];
    const float* b_edge_upd = (const float*)d_in[12];
    const float* W_node_upd = (const float*)d_in[13];
    const float* b_node_upd = (const float*)d_in[14];
    const float* W_score    = (const float*)d_in[15];
    const float* b_score    = (const float*)d_in[16];
    float* out = (float*)d_out;

    cudaFuncSetAttribute(k_eenc,  cudaFuncAttributeMaxDynamicSharedMemorySize, SMEM_EENC);
    cudaFuncSetAttribute(k_fused, cudaFuncAttributeMaxDynamicSharedMemorySize, SMEM_FUSED);

    k_prep <<<744, 256>>>(x, W_node_enc, u, W_glob_enc, b_glob_enc,
                          W_edge_upd, b_edge_upd, W_node_upd, b_node_upd, edge_index);
    k_eenc <<<16, 256, SMEM_EENC>>>(edge_attr, W_edge_enc, b_edge_enc);
    k_fused<<<512, 512, SMEM_FUSED>>>(spdist, edge_index,
                                      W_node_enc + 256*128, b_node_enc,
                                      W_score, b_score, out);
}